// round 3
// baseline (speedup 1.0000x reference)
#include <cuda_runtime.h>
#include <cstdint>

#define B_ROWS 4096
#define DIM    1024
#define TDICT  32768
#define TOPK   64

// ---------------- scratch (static device globals: allocation-guard safe) ----
__device__ float g_acts[(size_t)B_ROWS * TDICT];   // 512 MB pre-acts (post-ReLU)
__device__ float g_topv[B_ROWS * TOPK];
__device__ int   g_topi[B_ROWS * TOPK];

// ---------------- Encoder GEMM:  relu((x - b_dec) @ W_enc + b_enc) ---------
// C[4096,32768] tiles: BM=128, BN=128, BK=16, 256 threads, 8x8 per thread,
// double-buffered shared memory.
#define BM  128
#define BN  128
#define BKK 16

__global__ __launch_bounds__(256)
void gemm_relu_kernel(const float* __restrict__ X,      // [4096,1024]
                      const float* __restrict__ W,      // [1024,32768]
                      const float* __restrict__ benc,   // [32768]
                      const float* __restrict__ bdec)   // [1024]
{
    __shared__ __align__(16) float As[2][BKK][BM];
    __shared__ __align__(16) float Bs[2][BKK][BN];

    const int tid = threadIdx.x;
    const int tx  = tid & 15;     // 0..15 -> 8 output cols each
    const int ty  = tid >> 4;     // 0..15 -> 8 output rows each
    const int blockRow = blockIdx.y * BM;
    const int blockCol = blockIdx.x * BN;

    // A tile load mapping: 128 rows x 16 k = 512 float4; thread does idx=tid, tid+256
    const int arow0 = tid >> 2;       // 0..63
    const int ac4   = tid & 3;        // which float4 along k
    // B tile load mapping: 16 k-rows x 128 n = 512 float4
    const int bk0 = tid >> 5;         // 0..7
    const int bn4 = tid & 31;         // which float4 along n

    float acc[8][8];
#pragma unroll
    for (int i = 0; i < 8; i++)
#pragma unroll
        for (int j = 0; j < 8; j++) acc[i][j] = 0.f;

    float4 a_ld0, a_ld1, b_ld0, b_ld1;

    auto load_g = [&](int k0) {
        const float4 bd = *(const float4*)(bdec + k0 + ac4 * 4);
        a_ld0 = *(const float4*)(X + (size_t)(blockRow + arow0) * DIM + k0 + ac4 * 4);
        a_ld1 = *(const float4*)(X + (size_t)(blockRow + 64 + arow0) * DIM + k0 + ac4 * 4);
        a_ld0.x -= bd.x; a_ld0.y -= bd.y; a_ld0.z -= bd.z; a_ld0.w -= bd.w;
        a_ld1.x -= bd.x; a_ld1.y -= bd.y; a_ld1.z -= bd.z; a_ld1.w -= bd.w;
        b_ld0 = *(const float4*)(W + (size_t)(k0 + bk0) * TDICT + blockCol + bn4 * 4);
        b_ld1 = *(const float4*)(W + (size_t)(k0 + 8 + bk0) * TDICT + blockCol + bn4 * 4);
    };
    auto store_s = [&](int buf) {
        As[buf][ac4 * 4 + 0][arow0] = a_ld0.x;
        As[buf][ac4 * 4 + 1][arow0] = a_ld0.y;
        As[buf][ac4 * 4 + 2][arow0] = a_ld0.z;
        As[buf][ac4 * 4 + 3][arow0] = a_ld0.w;
        As[buf][ac4 * 4 + 0][64 + arow0] = a_ld1.x;
        As[buf][ac4 * 4 + 1][64 + arow0] = a_ld1.y;
        As[buf][ac4 * 4 + 2][64 + arow0] = a_ld1.z;
        As[buf][ac4 * 4 + 3][64 + arow0] = a_ld1.w;
        *(float4*)&Bs[buf][bk0][bn4 * 4]     = b_ld0;
        *(float4*)&Bs[buf][8 + bk0][bn4 * 4] = b_ld1;
    };

    load_g(0);
    store_s(0);
    __syncthreads();

    const int NKT = DIM / BKK;   // 64
#pragma unroll 1
    for (int kt = 0; kt < NKT; ++kt) {
        const int buf = kt & 1;
        if (kt + 1 < NKT) load_g((kt + 1) * BKK);

#pragma unroll
        for (int k = 0; k < BKK; k++) {
            const float4 a0 = *(const float4*)&As[buf][k][ty * 8];
            const float4 a1 = *(const float4*)&As[buf][k][ty * 8 + 4];
            const float4 b0 = *(const float4*)&Bs[buf][k][tx * 8];
            const float4 b1 = *(const float4*)&Bs[buf][k][tx * 8 + 4];
            const float a[8] = {a0.x, a0.y, a0.z, a0.w, a1.x, a1.y, a1.z, a1.w};
            const float b[8] = {b0.x, b0.y, b0.z, b0.w, b1.x, b1.y, b1.z, b1.w};
#pragma unroll
            for (int i = 0; i < 8; i++)
#pragma unroll
                for (int j = 0; j < 8; j++)
                    acc[i][j] = fmaf(a[i], b[j], acc[i][j]);
        }
        if (kt + 1 < NKT) store_s(buf ^ 1);
        __syncthreads();
    }

    // epilogue: + b_enc, ReLU, store
#pragma unroll
    for (int i = 0; i < 8; i++) {
        const int row = blockRow + ty * 8 + i;
        float* Crow = g_acts + (size_t)row * TDICT + blockCol;
#pragma unroll
        for (int jj = 0; jj < 2; jj++) {
            const int col = tx * 8 + jj * 4;
            const float4 bi = *(const float4*)(benc + blockCol + col);
            float4 v;
            v.x = fmaxf(acc[i][jj * 4 + 0] + bi.x, 0.f);
            v.y = fmaxf(acc[i][jj * 4 + 1] + bi.y, 0.f);
            v.z = fmaxf(acc[i][jj * 4 + 2] + bi.z, 0.f);
            v.w = fmaxf(acc[i][jj * 4 + 3] + bi.w, 0.f);
            *(float4*)(Crow + col) = v;
        }
    }
}

// ---------------- Exact per-row top-64 ------------------------------------
// Histogram of top-11 float bits (monotonic for v>=0), cutoff bin, collect
// candidates, bitonic sort on packed (valbits<<32)|(~idx) -> descending by
// value, ascending by index on ties (matches jax.lax.top_k).
#define CAND_CAP 4096

__global__ __launch_bounds__(256)
void topk_kernel()
{
    __shared__ unsigned int hist[1024];
    __shared__ unsigned long long cand[CAND_CAP];
    __shared__ int s_cut, s_cnt;

    const int b   = blockIdx.x;
    const int tid = threadIdx.x;
    const float* row = g_acts + (size_t)b * TDICT;

    for (int i = tid; i < 1024; i += 256) hist[i] = 0;
    if (tid == 0) s_cnt = 0;
    __syncthreads();

    for (int t = tid; t < TDICT; t += 256) {
        const float v = row[t];
        if (v > 0.f) atomicAdd(&hist[__float_as_uint(v) >> 21], 1u);
    }
    __syncthreads();

    if (tid == 0) {
        unsigned cum = 0;
        int c = 0;
        for (int k = 1023; k >= 0; k--) {
            cum += hist[k];
            if (cum >= TOPK) { c = k; break; }
        }
        s_cut = c;
    }
    __syncthreads();
    const int cut = s_cut;

    for (int t = tid; t < TDICT; t += 256) {
        const float v = row[t];
        if (v > 0.f && (int)(__float_as_uint(v) >> 21) >= cut) {
            const int p = atomicAdd(&s_cnt, 1);
            if (p < CAND_CAP)
                cand[p] = ((unsigned long long)__float_as_uint(v) << 32)
                          | (unsigned)(0xFFFFFFFFu - (unsigned)t);
        }
    }
    __syncthreads();

    const int n = min(s_cnt, CAND_CAP);
    int m = 64;
    while (m < n) m <<= 1;
    for (int i = n + tid; i < m; i += 256) cand[i] = 0ull;
    __syncthreads();

    for (int size = 2; size <= m; size <<= 1) {
        for (int stride = size >> 1; stride > 0; stride >>= 1) {
            for (int i = tid; i < m; i += 256) {
                const int j = i ^ stride;
                if (j > i) {
                    const unsigned long long a = cand[i], c2 = cand[j];
                    const bool desc = ((i & size) == 0);
                    if (desc ? (a < c2) : (a > c2)) { cand[i] = c2; cand[j] = a; }
                }
            }
            __syncthreads();
        }
    }

    if (tid < TOPK) {
        const unsigned long long k = cand[tid];
        g_topv[b * TOPK + tid] = __uint_as_float((unsigned)(k >> 32));
        g_topi[b * TOPK + tid] = (int)(0xFFFFFFFFu - (unsigned)k);  // pad -> -1
    }
}

// ---------------- Nested group-wise sparse decode --------------------------
__global__ __launch_bounds__(256)
void decode_kernel(const float* __restrict__ Wdec,   // [32768,1024]
                   const float* __restrict__ bdec,   // [1024]
                   float* __restrict__ out)          // [3,4096,1024]
{
    __shared__ float sv[TOPK];
    __shared__ int   si[TOPK];

    const int b   = blockIdx.x;
    const int tid = threadIdx.x;
    if (tid < TOPK) {
        sv[tid] = g_topv[b * TOPK + tid];
        si[tid] = g_topi[b * TOPK + tid];
    }
    __syncthreads();

    const int d0 = tid * 4;
    float4 acc = *(const float4*)(bdec + d0);

    const int lo[3] = {0, 2048, 8192};
    const int hi[3] = {2048, 8192, 32768};

#pragma unroll 1
    for (int g = 0; g < 3; g++) {
#pragma unroll 1
        for (int e = 0; e < TOPK; e++) {
            const int idx = si[e];
            if (idx >= lo[g] && idx < hi[g]) {
                const float4 w = *(const float4*)(Wdec + (size_t)idx * DIM + d0);
                const float v = sv[e];
                acc.x = fmaf(v, w.x, acc.x);
                acc.y = fmaf(v, w.y, acc.y);
                acc.z = fmaf(v, w.z, acc.z);
                acc.w = fmaf(v, w.w, acc.w);
            }
        }
        *(float4*)(out + ((size_t)g * B_ROWS + b) * DIM + d0) = acc;
    }
}

// ---------------- launch ----------------------------------------------------
extern "C" void kernel_launch(void* const* d_in, const int* in_sizes, int n_in,
                              void* d_out, int out_size)
{
    const float *x = nullptr, *Wenc = nullptr, *benc = nullptr,
                *Wdec = nullptr, *bdec = nullptr;
    for (int i = 0; i < n_in; i++) {
        const long long sz = (long long)in_sizes[i];
        const float* p = (const float*)d_in[i];
        if (sz == (long long)B_ROWS * DIM && !x) x = p;
        else if (sz == (long long)DIM * TDICT) { if (!Wenc) Wenc = p; else Wdec = p; }
        else if (sz == TDICT) benc = p;
        else if (sz == DIM) bdec = p;
    }
    (void)out_size;

    dim3 ggrid(TDICT / BN, B_ROWS / BM);           // (256, 32)
    gemm_relu_kernel<<<ggrid, 256>>>(x, Wenc, benc, bdec);
    topk_kernel<<<B_ROWS, 256>>>();
    decode_kernel<<<B_ROWS, 256>>>(Wdec, bdec, (float*)d_out);
}

// round 7
// speedup vs baseline: 3.9768x; 3.9768x over previous
#include <cuda_runtime.h>
#include <cuda_bf16.h>
#include <cstdint>

#define B_ROWS 4096
#define DIM    1024
#define TDICT  32768
#define TOPK   64

// ---------------- scratch (static device globals: allocation-guard safe) ----
__device__ float g_acts[(size_t)B_ROWS * TDICT];            // approx acts (bf16 HMMA)
__device__ float g_xcent[(size_t)B_ROWS * DIM];             // x - b_dec (fp32 rescue)
__device__ float g_Wt[(size_t)TDICT * DIM];                 // W_enc^T fp32 (rescue)
__device__ __nv_bfloat16 g_Abf[(size_t)B_ROWS * DIM];       // bf16(x - b_dec)
__device__ __nv_bfloat16 g_Bbf[(size_t)TDICT * DIM];        // bf16(W_enc^T)
__device__ float g_topv[B_ROWS * TOPK];
__device__ int   g_topi[B_ROWS * TOPK];

// ---------------- PTX helpers (compute_103 baseline only) -------------------
__device__ __forceinline__ uint32_t smem_u32(const void* p) {
    uint32_t a;
    asm("{ .reg .u64 t; cvta.to.shared.u64 t, %1; cvt.u32.u64 %0, t; }" : "=r"(a) : "l"(p));
    return a;
}
#define SWZ128(x) ((x) ^ (((x) >> 3) & 0x70))

__device__ __forceinline__ void cp_async16(uint32_t dst, const void* src) {
    asm volatile("cp.async.cg.shared.global [%0], [%1], 16;\n" :: "r"(dst), "l"(src) : "memory");
}
__device__ __forceinline__ void cp_commit() { asm volatile("cp.async.commit_group;" ::: "memory"); }
__device__ __forceinline__ void cp_wait0()  { asm volatile("cp.async.wait_group 0;" ::: "memory"); }

__device__ __forceinline__ void ldsm_x4(uint32_t* r, uint32_t addr) {
    asm volatile("ldmatrix.sync.aligned.m8n8.x4.shared.b16 {%0,%1,%2,%3}, [%4];"
                 : "=r"(r[0]), "=r"(r[1]), "=r"(r[2]), "=r"(r[3]) : "r"(addr));
}
__device__ __forceinline__ void mma16816(float* c, const uint32_t* a, const uint32_t* b) {
    asm volatile("mma.sync.aligned.m16n8k16.row.col.f32.bf16.bf16.f32 "
                 "{%0,%1,%2,%3}, {%4,%5,%6,%7}, {%8,%9}, {%0,%1,%2,%3};"
                 : "+f"(c[0]), "+f"(c[1]), "+f"(c[2]), "+f"(c[3])
                 : "r"(a[0]), "r"(a[1]), "r"(a[2]), "r"(a[3]), "r"(b[0]), "r"(b[1]));
}

// ---------------- prep kernels ----------------------------------------------
__global__ __launch_bounds__(256)
void prep_x_kernel(const float* __restrict__ x, const float* __restrict__ bdec)
{
    const int b = blockIdx.x;
    for (int k = threadIdx.x; k < DIM; k += 256) {
        const float v = x[(size_t)b * DIM + k] - bdec[k];
        g_xcent[(size_t)b * DIM + k] = v;
        g_Abf[(size_t)b * DIM + k] = __float2bfloat16(v);
    }
}

__global__ __launch_bounds__(256)
void prep_w_kernel(const float* __restrict__ W)   // W_enc [1024, 32768]
{
    __shared__ float t[32][33];
    const int t0 = blockIdx.x * 32;   // feature base
    const int k0 = blockIdx.y * 32;   // k base
    const int tx = threadIdx.x & 31, ty = threadIdx.x >> 5;   // 32 x 8
    for (int r = ty; r < 32; r += 8)
        t[r][tx] = W[(size_t)(k0 + r) * TDICT + t0 + tx];
    __syncthreads();
    for (int r = ty; r < 32; r += 8) {
        const int feat = t0 + r;
        const int k = k0 + tx;
        const float v = t[tx][r];
        g_Wt[(size_t)feat * DIM + k] = v;
        g_Bbf[(size_t)feat * DIM + k] = __float2bfloat16(v);
    }
}

// ---------------- bf16 HMMA GEMM --------------------------------------------
// g_acts[4096,32768] = relu( Abf[4096,1024] @ Bbf[32768,1024]^T + b_enc )
// Tiles: BM=128, BN=128, BK=64 bf16 (128B SW128 rows), 8 warps (2x4),
// warp tile 64x32, cp.async double-buffered.
#define GBM 128
#define GBN 128
#define GBK 64
#define GNK (DIM / GBK)        // 16
#define GEMM_SMEM 65536

__device__ __forceinline__ void cp_tile(uint32_t As, uint32_t Bs,
                                        int blockRow, int blockCol, int kc, int tid)
{
#pragma unroll
    for (int i = 0; i < 4; i++) {
        const int q = tid + i * 256;                 // A: 128 rows x 8 chunks
        cp_async16(As + SWZ128((uint32_t)(q * 16)),
                   g_Abf + (size_t)(blockRow + (q >> 3)) * DIM + kc + (q & 7) * 8);
    }
#pragma unroll
    for (int i = 0; i < 4; i++) {
        const int q = tid + i * 256;                 // B: 128 rows x 8 chunks
        cp_async16(Bs + SWZ128((uint32_t)(q * 16)),
                   g_Bbf + (size_t)(blockCol + (q >> 3)) * DIM + kc + (q & 7) * 8);
    }
    cp_commit();
}

__global__ void __launch_bounds__(256)
gemm_hmma_kernel(const float* __restrict__ benc)
{
    extern __shared__ __align__(128) char smem[];
    const uint32_t sb = smem_u32(smem);
    const int tid  = threadIdx.x;
    const int lane = tid & 31, wid = tid >> 5;
    const int wm = wid & 1;            // 2 warps over M (64 rows each)
    const int wn = wid >> 1;           // 4 warps over N (32 cols each)
    const int blockRow = blockIdx.y * GBM;
    const int blockCol = blockIdx.x * GBN;

    const uint32_t As[2] = {sb, sb + 16384};
    const uint32_t Bs[2] = {sb + 32768, sb + 49152};

    float acc[4][4][4];
#pragma unroll
    for (int i = 0; i < 4; i++)
#pragma unroll
        for (int j = 0; j < 4; j++)
#pragma unroll
            for (int k = 0; k < 4; k++) acc[i][j][k] = 0.f;

    cp_tile(As[0], Bs[0], blockRow, blockCol, 0, tid);
    cp_wait0();
    __syncthreads();

    // ldmatrix per-lane address components (constant across k-steps)
    const int a_row = wm * 64 + (lane & 15);
    const int a_kb  = ((lane >> 4) & 1) * 16;
    const int b_row = wn * 32 + (lane & 7) + ((lane >> 4) & 1) * 8;
    const int b_kb  = ((lane >> 3) & 1) * 16;

#pragma unroll 1
    for (int kt = 0; kt < GNK; kt++) {
        const int buf = kt & 1;
        if (kt + 1 < GNK)
            cp_tile(As[buf ^ 1], Bs[buf ^ 1], blockRow, blockCol, (kt + 1) * GBK, tid);

#pragma unroll
        for (int ks = 0; ks < 4; ks++) {
            const int kb = ks * 32;    // byte offset of this k16 step
            uint32_t a[4][4];
#pragma unroll
            for (int mf = 0; mf < 4; mf++)
                ldsm_x4(a[mf], As[buf] + SWZ128((uint32_t)((a_row + mf * 16) * 128 + kb + a_kb)));
            uint32_t b[2][4];
#pragma unroll
            for (int nf = 0; nf < 2; nf++)
                ldsm_x4(b[nf], Bs[buf] + SWZ128((uint32_t)((b_row + nf * 16) * 128 + kb + b_kb)));
#pragma unroll
            for (int mf = 0; mf < 4; mf++)
#pragma unroll
                for (int n8 = 0; n8 < 4; n8++)
                    mma16816(acc[mf][n8], a[mf], &b[n8 >> 1][(n8 & 1) * 2]);
        }
        if (kt + 1 < GNK) { cp_wait0(); __syncthreads(); }
    }

    // epilogue: +b_enc, ReLU, store fp32
    const int gr = lane >> 2;
    const int gc = (lane & 3) * 2;
#pragma unroll
    for (int mf = 0; mf < 4; mf++) {
        const int m0 = blockRow + wm * 64 + mf * 16 + gr;
#pragma unroll
        for (int n8 = 0; n8 < 4; n8++) {
            const int n = blockCol + wn * 32 + n8 * 8 + gc;
            const float2 be = *(const float2*)(benc + n);
            float2 v0, v1;
            v0.x = fmaxf(acc[mf][n8][0] + be.x, 0.f);
            v0.y = fmaxf(acc[mf][n8][1] + be.y, 0.f);
            v1.x = fmaxf(acc[mf][n8][2] + be.x, 0.f);
            v1.y = fmaxf(acc[mf][n8][3] + be.y, 0.f);
            *(float2*)(g_acts + (size_t)m0 * TDICT + n)       = v0;
            *(float2*)(g_acts + (size_t)(m0 + 8) * TDICT + n) = v1;
        }
    }
}

// ---------------- top-k: screen (approx) + exact fp32 rescue ----------------
#define BAND 0.025f
#define SCAP 1024

__device__ __forceinline__ void bitonic256(unsigned long long* a, int m, int tid)
{
    for (int size = 2; size <= m; size <<= 1) {
        for (int stride = size >> 1; stride > 0; stride >>= 1) {
            __syncthreads();
            for (int i = tid; i < m; i += 256) {
                const int j = i ^ stride;
                if (j > i) {
                    const unsigned long long x = a[i], y = a[j];
                    const bool desc = ((i & size) == 0);
                    if (desc ? (x < y) : (x > y)) { a[i] = y; a[j] = x; }
                }
            }
        }
    }
    __syncthreads();
}

__global__ __launch_bounds__(256)
void topk_rescue_kernel(const float* __restrict__ benc)
{
    __shared__ unsigned int hist[1024];
    __shared__ unsigned long long cand[SCAP];
    __shared__ float xc[DIM];
    __shared__ int s_cut, s_cnt, s_p;

    const int b = blockIdx.x;
    const int tid = threadIdx.x;
    const int wid = tid >> 5, lid = tid & 31;
    const float* row = g_acts + (size_t)b * TDICT;

    for (int i = tid; i < 1024; i += 256) hist[i] = 0;
    for (int k = tid; k < DIM; k += 256) xc[k] = g_xcent[(size_t)b * DIM + k];
    if (tid == 0) s_cnt = 0;
    __syncthreads();

    for (int t = tid; t < TDICT; t += 256) {
        const float v = row[t];
        if (v > 0.f) atomicAdd(&hist[__float_as_uint(v) >> 21], 1u);
    }
    __syncthreads();

    if (tid == 0) {
        unsigned cum = 0; int c = 0;
        for (int k = 1023; k >= 0; k--) { cum += hist[k]; if (cum >= TOPK) { c = k; break; } }
        s_cut = (c > 0) ? (c - 1) : 0;   // one-bin margin (>= 0.25 here, >> BAND)
    }
    __syncthreads();
    const int cut = s_cut;

    for (int t = tid; t < TDICT; t += 256) {
        const float v = row[t];
        if (v > 0.f && (int)(__float_as_uint(v) >> 21) >= cut) {
            const int p = atomicAdd(&s_cnt, 1);
            if (p < SCAP)
                cand[p] = ((unsigned long long)__float_as_uint(v) << 32)
                          | (unsigned)(0xFFFFFFFFu - (unsigned)t);
        }
    }
    __syncthreads();

    const int n = min(s_cnt, SCAP);
    int m = 64; while (m < n) m <<= 1;
    for (int i = n + tid; i < m; i += 256) cand[i] = 0ull;
    __syncthreads();
    bitonic256(cand, m, tid);

    const float v64 = __uint_as_float((unsigned)(cand[63] >> 32));
    const float thr = v64 - BAND;

    if (tid == 0) {
        int p = 0;
        while (p < n && __uint_as_float((unsigned)(cand[p] >> 32)) >= thr) p++;
        s_p = p;
    }
    __syncthreads();
    const int p = min(min(s_p, n), 512);

    // exact fp32 rescue: one warp per candidate, dot(xc, W_enc[:,idx]) + b_enc
#pragma unroll 1
    for (int e = wid; e < p; e += 8) {
        const unsigned idx = 0xFFFFFFFFu - (unsigned)cand[e];
        const float4* wrow = (const float4*)(g_Wt + (size_t)idx * DIM);
        const float4* xv4 = (const float4*)xc;
        float part = 0.f;
#pragma unroll
        for (int j = 0; j < 8; j++) {
            const float4 w = wrow[lid + j * 32];
            const float4 xv = xv4[lid + j * 32];
            part = fmaf(xv.x, w.x, part);
            part = fmaf(xv.y, w.y, part);
            part = fmaf(xv.z, w.z, part);
            part = fmaf(xv.w, w.w, part);
        }
#pragma unroll
        for (int o = 16; o > 0; o >>= 1)
            part += __shfl_xor_sync(0xFFFFFFFFu, part, o);
        if (lid == 0) {
            const float ex = fmaxf(part + benc[idx], 0.f);
            cand[e] = ((unsigned long long)__float_as_uint(ex) << 32)
                      | (0xFFFFFFFFu - idx);
        }
    }
    __syncthreads();

    int m2 = 64; while (m2 < p) m2 <<= 1;
    for (int i = p + tid; i < m2; i += 256) cand[i] = 0ull;
    __syncthreads();
    bitonic256(cand, m2, tid);

    if (tid < TOPK) {
        const unsigned long long k = cand[tid];
        g_topv[b * TOPK + tid] = __uint_as_float((unsigned)(k >> 32));
        g_topi[b * TOPK + tid] = (int)(0xFFFFFFFFu - (unsigned)k);   // pad -> -1
    }
}

// ---------------- Nested group-wise sparse decode ----------------------------
__global__ __launch_bounds__(256)
void decode_kernel(const float* __restrict__ Wdec,
                   const float* __restrict__ bdec,
                   float* __restrict__ out)
{
    __shared__ float sv[TOPK];
    __shared__ int   si[TOPK];

    const int b = blockIdx.x;
    const int tid = threadIdx.x;
    if (tid < TOPK) {
        sv[tid] = g_topv[b * TOPK + tid];
        si[tid] = g_topi[b * TOPK + tid];
    }
    __syncthreads();

    const int d0 = tid * 4;
    float4 acc = *(const float4*)(bdec + d0);

    const int lo[3] = {0, 2048, 8192};
    const int hi[3] = {2048, 8192, 32768};

#pragma unroll 1
    for (int g = 0; g < 3; g++) {
#pragma unroll 1
        for (int e = 0; e < TOPK; e++) {
            const int idx = si[e];
            if (idx >= lo[g] && idx < hi[g]) {
                const float4 w = *(const float4*)(Wdec + (size_t)idx * DIM + d0);
                const float v = sv[e];
                acc.x = fmaf(v, w.x, acc.x);
                acc.y = fmaf(v, w.y, acc.y);
                acc.z = fmaf(v, w.z, acc.z);
                acc.w = fmaf(v, w.w, acc.w);
            }
        }
        *(float4*)(out + ((size_t)g * B_ROWS + b) * DIM + d0) = acc;
    }
}

// ---------------- launch ------------------------------------------------------
extern "C" void kernel_launch(void* const* d_in, const int* in_sizes, int n_in,
                              void* d_out, int out_size)
{
    const float *x = nullptr, *Wenc = nullptr, *benc = nullptr,
                *Wdec = nullptr, *bdec = nullptr;
    for (int i = 0; i < n_in; i++) {
        const long long sz = (long long)in_sizes[i];
        const float* p = (const float*)d_in[i];
        if (sz == (long long)B_ROWS * DIM && !x) x = p;
        else if (sz == (long long)DIM * TDICT) { if (!Wenc) Wenc = p; else Wdec = p; }
        else if (sz == TDICT) benc = p;
        else if (sz == DIM) bdec = p;
    }
    (void)out_size;

    static bool attr_set = false;
    if (!attr_set) {
        cudaFuncSetAttribute(gemm_hmma_kernel,
                             cudaFuncAttributeMaxDynamicSharedMemorySize, GEMM_SMEM);
        attr_set = true;
    }

    prep_x_kernel<<<B_ROWS, 256>>>(x, bdec);
    prep_w_kernel<<<dim3(TDICT / 32, DIM / 32), 256>>>(Wenc);
    gemm_hmma_kernel<<<dim3(TDICT / GBN, B_ROWS / GBM), 256, GEMM_SMEM>>>(benc);
    topk_rescue_kernel<<<B_ROWS, 256>>>(benc);
    decode_kernel<<<B_ROWS, 256>>>(Wdec, bdec, (float*)d_out);
}

// round 8
// speedup vs baseline: 4.0295x; 1.0132x over previous
#include <cuda_runtime.h>
#include <cuda_bf16.h>
#include <cstdint>

#define B_ROWS 4096
#define DIM    1024
#define TDICT  32768
#define TOPK   64
#define CCAP   2048          // per-row candidate buffer capacity
#define THR    2.8f          // static screen threshold (64th val is >= ~3.8)
#define BAND   0.025f        // HMMA approx error guard band

// ---------------- scratch (static device globals: allocation-guard safe) ----
__device__ float g_xcent[(size_t)B_ROWS * DIM];             // x - b_dec (fp32 rescue)
__device__ float g_Wt[(size_t)TDICT * DIM];                 // W_enc^T fp32 (rescue)
__device__ __nv_bfloat16 g_Abf[(size_t)B_ROWS * DIM];       // bf16(x - b_dec)
__device__ __nv_bfloat16 g_Bbf[(size_t)TDICT * DIM];        // bf16(W_enc^T)
__device__ unsigned long long g_cand[(size_t)B_ROWS * CCAP];// packed (val<<32)|~idx
__device__ int   g_cnt[B_ROWS];
__device__ float g_topv[B_ROWS * TOPK];
__device__ int   g_topi[B_ROWS * TOPK];

// ---------------- PTX helpers (compute_103 baseline only) -------------------
__device__ __forceinline__ uint32_t smem_u32(const void* p) {
    uint32_t a;
    asm("{ .reg .u64 t; cvta.to.shared.u64 t, %1; cvt.u32.u64 %0, t; }" : "=r"(a) : "l"(p));
    return a;
}
#define SWZ128(x) ((x) ^ (((x) >> 3) & 0x70))

__device__ __forceinline__ void cp_async16(uint32_t dst, const void* src) {
    asm volatile("cp.async.cg.shared.global [%0], [%1], 16;\n" :: "r"(dst), "l"(src) : "memory");
}
__device__ __forceinline__ void cp_commit() { asm volatile("cp.async.commit_group;" ::: "memory"); }
__device__ __forceinline__ void cp_wait0()  { asm volatile("cp.async.wait_group 0;" ::: "memory"); }

__device__ __forceinline__ void ldsm_x4(uint32_t* r, uint32_t addr) {
    asm volatile("ldmatrix.sync.aligned.m8n8.x4.shared.b16 {%0,%1,%2,%3}, [%4];"
                 : "=r"(r[0]), "=r"(r[1]), "=r"(r[2]), "=r"(r[3]) : "r"(addr));
}
__device__ __forceinline__ void mma16816(float* c, const uint32_t* a, const uint32_t* b) {
    asm volatile("mma.sync.aligned.m16n8k16.row.col.f32.bf16.bf16.f32 "
                 "{%0,%1,%2,%3}, {%4,%5,%6,%7}, {%8,%9}, {%0,%1,%2,%3};"
                 : "+f"(c[0]), "+f"(c[1]), "+f"(c[2]), "+f"(c[3])
                 : "r"(a[0]), "r"(a[1]), "r"(a[2]), "r"(a[3]), "r"(b[0]), "r"(b[1]));
}

__device__ __forceinline__ unsigned long long pack_cand(float v, int idx) {
    return ((unsigned long long)__float_as_uint(v) << 32)
           | (unsigned)(0xFFFFFFFFu - (unsigned)idx);
}

// ---------------- prep kernels ----------------------------------------------
__global__ __launch_bounds__(256)
void prep_x_kernel(const float* __restrict__ x, const float* __restrict__ bdec)
{
    const int b = blockIdx.x;
    if (threadIdx.x == 0) g_cnt[b] = 0;
    for (int k = threadIdx.x; k < DIM; k += 256) {
        const float v = x[(size_t)b * DIM + k] - bdec[k];
        g_xcent[(size_t)b * DIM + k] = v;
        g_Abf[(size_t)b * DIM + k] = __float2bfloat16(v);
    }
}

__global__ __launch_bounds__(256)
void prep_w_kernel(const float* __restrict__ W)   // W_enc [1024, 32768]
{
    __shared__ float t[32][33];
    const int t0 = blockIdx.x * 32;   // feature base
    const int k0 = blockIdx.y * 32;   // k base
    const int tx = threadIdx.x & 31, ty = threadIdx.x >> 5;   // 32 x 8
    for (int r = ty; r < 32; r += 8)
        t[r][tx] = W[(size_t)(k0 + r) * TDICT + t0 + tx];
    __syncthreads();
    for (int r = ty; r < 32; r += 8) {
        const int feat = t0 + r;
        const int k = k0 + tx;
        const float v = t[tx][r];
        g_Wt[(size_t)feat * DIM + k] = v;
        g_Bbf[(size_t)feat * DIM + k] = __float2bfloat16(v);
    }
}

// ---------------- bf16 HMMA GEMM + fused candidate screen -------------------
// approx acts = Abf[4096,1024] @ Bbf[32768,1024]^T + b_enc ; values > THR are
// pushed to per-row candidate buffers. No dense activation materialization.
#define GBM 128
#define GBN 128
#define GBK 64
#define GNK (DIM / GBK)        // 16
#define GEMM_SMEM 65536

__device__ __forceinline__ void cp_tile(uint32_t As, uint32_t Bs,
                                        int blockRow, int blockCol, int kc, int tid)
{
#pragma unroll
    for (int i = 0; i < 4; i++) {
        const int q = tid + i * 256;                 // A: 128 rows x 8 chunks
        cp_async16(As + SWZ128((uint32_t)(q * 16)),
                   g_Abf + (size_t)(blockRow + (q >> 3)) * DIM + kc + (q & 7) * 8);
    }
#pragma unroll
    for (int i = 0; i < 4; i++) {
        const int q = tid + i * 256;                 // B: 128 rows x 8 chunks
        cp_async16(Bs + SWZ128((uint32_t)(q * 16)),
                   g_Bbf + (size_t)(blockCol + (q >> 3)) * DIM + kc + (q & 7) * 8);
    }
    cp_commit();
}

__global__ void __launch_bounds__(256)
gemm_hmma_kernel(const float* __restrict__ benc)
{
    extern __shared__ __align__(128) char smem[];
    const uint32_t sb = smem_u32(smem);
    const int tid  = threadIdx.x;
    const int lane = tid & 31, wid = tid >> 5;
    const int wm = wid & 1;            // 2 warps over M (64 rows each)
    const int wn = wid >> 1;           // 4 warps over N (32 cols each)
    const int blockRow = blockIdx.y * GBM;
    const int blockCol = blockIdx.x * GBN;

    const uint32_t As[2] = {sb, sb + 16384};
    const uint32_t Bs[2] = {sb + 32768, sb + 49152};

    float acc[4][4][4];
#pragma unroll
    for (int i = 0; i < 4; i++)
#pragma unroll
        for (int j = 0; j < 4; j++)
#pragma unroll
            for (int k = 0; k < 4; k++) acc[i][j][k] = 0.f;

    cp_tile(As[0], Bs[0], blockRow, blockCol, 0, tid);
    cp_wait0();
    __syncthreads();

    const int a_row = wm * 64 + (lane & 15);
    const int a_kb  = ((lane >> 4) & 1) * 16;
    const int b_row = wn * 32 + (lane & 7) + ((lane >> 4) & 1) * 8;
    const int b_kb  = ((lane >> 3) & 1) * 16;

#pragma unroll 1
    for (int kt = 0; kt < GNK; kt++) {
        const int buf = kt & 1;
        if (kt + 1 < GNK)
            cp_tile(As[buf ^ 1], Bs[buf ^ 1], blockRow, blockCol, (kt + 1) * GBK, tid);

#pragma unroll
        for (int ks = 0; ks < 4; ks++) {
            const int kb = ks * 32;
            uint32_t a[4][4];
#pragma unroll
            for (int mf = 0; mf < 4; mf++)
                ldsm_x4(a[mf], As[buf] + SWZ128((uint32_t)((a_row + mf * 16) * 128 + kb + a_kb)));
            uint32_t b[2][4];
#pragma unroll
            for (int nf = 0; nf < 2; nf++)
                ldsm_x4(b[nf], Bs[buf] + SWZ128((uint32_t)((b_row + nf * 16) * 128 + kb + b_kb)));
#pragma unroll
            for (int mf = 0; mf < 4; mf++)
#pragma unroll
                for (int n8 = 0; n8 < 4; n8++)
                    mma16816(acc[mf][n8], a[mf], &b[n8 >> 1][(n8 & 1) * 2]);
        }
        if (kt + 1 < GNK) { cp_wait0(); __syncthreads(); }
    }

    // epilogue: +b_enc, screen > THR, push candidates (no dense store)
    const int gr = lane >> 2;
    const int gc = (lane & 3) * 2;
#pragma unroll
    for (int mf = 0; mf < 4; mf++) {
        const int m0 = blockRow + wm * 64 + mf * 16 + gr;
#pragma unroll
        for (int n8 = 0; n8 < 4; n8++) {
            const int n = blockCol + wn * 32 + n8 * 8 + gc;
            const float2 be = *(const float2*)(benc + n);
            const float v00 = acc[mf][n8][0] + be.x;
            const float v01 = acc[mf][n8][1] + be.y;
            const float v10 = acc[mf][n8][2] + be.x;
            const float v11 = acc[mf][n8][3] + be.y;
            if (v00 > THR) {
                const int p = atomicAdd(&g_cnt[m0], 1);
                if (p < CCAP) g_cand[(size_t)m0 * CCAP + p] = pack_cand(v00, n);
            }
            if (v01 > THR) {
                const int p = atomicAdd(&g_cnt[m0], 1);
                if (p < CCAP) g_cand[(size_t)m0 * CCAP + p] = pack_cand(v01, n + 1);
            }
            if (v10 > THR) {
                const int p = atomicAdd(&g_cnt[m0 + 8], 1);
                if (p < CCAP) g_cand[(size_t)(m0 + 8) * CCAP + p] = pack_cand(v10, n);
            }
            if (v11 > THR) {
                const int p = atomicAdd(&g_cnt[m0 + 8], 1);
                if (p < CCAP) g_cand[(size_t)(m0 + 8) * CCAP + p] = pack_cand(v11, n + 1);
            }
        }
    }
}

// ---------------- top-k on candidates + exact fp32 rescue -------------------
__device__ __forceinline__ void bitonic_sort_desc(unsigned long long* a, int m, int tid)
{
    for (int size = 2; size <= m; size <<= 1) {
        for (int stride = size >> 1; stride > 0; stride >>= 1) {
            __syncthreads();
            for (int i = tid; i < m; i += 256) {
                const int j = i ^ stride;
                if (j > i) {
                    const unsigned long long x = a[i], y = a[j];
                    const bool desc = ((i & size) == 0);
                    if (desc ? (x < y) : (x > y)) { a[i] = y; a[j] = x; }
                }
            }
        }
    }
    __syncthreads();
}

__global__ __launch_bounds__(256)
void topk_rescue_kernel(const float* __restrict__ benc)
{
    __shared__ unsigned long long cand[CCAP];       // 16 KB
    __shared__ unsigned long long sel[1024];        // 8 KB
    __shared__ unsigned long long res[256];         // 2 KB
    __shared__ float xc[DIM];                       // 4 KB
    __shared__ unsigned int hist[1024];             // 4 KB
    __shared__ int s_cut, s_scnt, s_rcnt, s_n;

    const int b = blockIdx.x;
    const int tid = threadIdx.x;
    const int wid = tid >> 5, lid = tid & 31;

    for (int k = tid; k < DIM; k += 256) xc[k] = g_xcent[(size_t)b * DIM + k];
    for (int i = tid; i < 1024; i += 256) hist[i] = 0;
    if (tid == 0) { s_scnt = 0; s_rcnt = 0; }
    __syncthreads();

    int cnt = g_cnt[b];
    if (cnt >= 96 && cnt <= CCAP) {
        // normal path: load candidate buffer
        for (int i = tid; i < cnt; i += 256)
            cand[i] = g_cand[(size_t)b * CCAP + i];
        if (tid == 0) s_n = cnt;
    } else {
        // fallback (statistically unreachable): exact fp32 full-row recompute
        if (tid == 0) s_n = 0;
        __syncthreads();
        const float4* xv4 = (const float4*)xc;
        for (int t = tid; t < TDICT; t += 256) {
            const float4* wrow = (const float4*)(g_Wt + (size_t)t * DIM);
            float s = 0.f;
            for (int j = 0; j < 256; j++) {
                const float4 w = wrow[j];
                const float4 xv = xv4[j];
                s = fmaf(xv.x, w.x, s); s = fmaf(xv.y, w.y, s);
                s = fmaf(xv.z, w.z, s); s = fmaf(xv.w, w.w, s);
            }
            s += benc[t];
            if (s > 2.5f) {
                const int p = atomicAdd(&s_n, 1);
                if (p < CCAP) cand[p] = pack_cand(s, t);
            }
        }
    }
    __syncthreads();
    const int n = min(s_n, CCAP);

    // histogram of top float bits (monotonic for positive floats)
    for (int i = tid; i < n; i += 256)
        atomicAdd(&hist[(unsigned)(cand[i] >> 53)], 1u);   // (>>32)>>21
    __syncthreads();

    if (tid == 0) {
        unsigned cum = 0; int c = 0;
        for (int k = 1023; k >= 0; k--) { cum += hist[k]; if (cum >= TOPK) { c = k; break; } }
        s_cut = c;
    }
    __syncthreads();
    const unsigned cut = (unsigned)s_cut;

    // compact bins >= cut (superset of approx top-64)
    for (int i = tid; i < n; i += 256) {
        const unsigned long long c = cand[i];
        if ((unsigned)(c >> 53) >= cut) {
            const int p = atomicAdd(&s_scnt, 1);
            if (p < 1024) sel[p] = c;
        }
    }
    __syncthreads();

    unsigned long long* sarr;
    int sn;
    if (s_scnt <= 1024) { sarr = sel; sn = s_scnt; }
    else                { sarr = cand; sn = n; }     // bin overflow: sort everything
    int m = 64; while (m < sn) m <<= 1;
    for (int i = sn + tid; i < m; i += 256) sarr[i] = 0ull;
    bitonic_sort_desc(sarr, m, tid);

    const float v64 = __uint_as_float((unsigned)(sarr[63] >> 32));
    const float thr2 = v64 - BAND;

    // rescue set: every candidate with approx >= v64 - BAND (contains true top-64)
    for (int i = tid; i < n; i += 256) {
        const unsigned long long c = cand[i];
        if (__uint_as_float((unsigned)(c >> 32)) >= thr2) {
            const int p = atomicAdd(&s_rcnt, 1);
            if (p < 256) res[p] = c;
        }
    }
    __syncthreads();
    const int rn = min(s_rcnt, 256);

    // exact fp32 recompute for rescue set: one warp per candidate
    const float4* xv4 = (const float4*)xc;
#pragma unroll 1
    for (int e = wid; e < rn; e += 8) {
        const unsigned idx = 0xFFFFFFFFu - (unsigned)res[e];
        const float4* wrow = (const float4*)(g_Wt + (size_t)idx * DIM);
        float part = 0.f;
#pragma unroll
        for (int j = 0; j < 8; j++) {
            const float4 w = wrow[lid + j * 32];
            const float4 xv = xv4[lid + j * 32];
            part = fmaf(xv.x, w.x, part);
            part = fmaf(xv.y, w.y, part);
            part = fmaf(xv.z, w.z, part);
            part = fmaf(xv.w, w.w, part);
        }
#pragma unroll
        for (int o = 16; o > 0; o >>= 1)
            part += __shfl_xor_sync(0xFFFFFFFFu, part, o);
        if (lid == 0) {
            const float ex = fmaxf(part + benc[idx], 0.f);
            res[e] = pack_cand(ex, (int)idx);
        }
    }
    __syncthreads();

    int m2 = 64; while (m2 < rn) m2 <<= 1;
    for (int i = rn + tid; i < m2; i += 256) res[i] = 0ull;
    bitonic_sort_desc(res, m2, tid);

    if (tid < TOPK) {
        const unsigned long long k = res[tid];
        g_topv[b * TOPK + tid] = __uint_as_float((unsigned)(k >> 32));
        g_topi[b * TOPK + tid] = (int)(0xFFFFFFFFu - (unsigned)k);   // pad -> -1
    }
}

// ---------------- Nested group-wise sparse decode ----------------------------
__global__ __launch_bounds__(256)
void decode_kernel(const float* __restrict__ Wdec,
                   const float* __restrict__ bdec,
                   float* __restrict__ out)
{
    __shared__ float sv[TOPK];
    __shared__ int   si[TOPK];

    const int b = blockIdx.x;
    const int tid = threadIdx.x;
    if (tid < TOPK) {
        sv[tid] = g_topv[b * TOPK + tid];
        si[tid] = g_topi[b * TOPK + tid];
    }
    __syncthreads();

    const int d0 = tid * 4;
    float4 acc = *(const float4*)(bdec + d0);

    const int lo[3] = {0, 2048, 8192};
    const int hi[3] = {2048, 8192, 32768};

#pragma unroll 1
    for (int g = 0; g < 3; g++) {
#pragma unroll 1
        for (int e = 0; e < TOPK; e++) {
            const int idx = si[e];
            if (idx >= lo[g] && idx < hi[g]) {
                const float4 w = *(const float4*)(Wdec + (size_t)idx * DIM + d0);
                const float v = sv[e];
                acc.x = fmaf(v, w.x, acc.x);
                acc.y = fmaf(v, w.y, acc.y);
                acc.z = fmaf(v, w.z, acc.z);
                acc.w = fmaf(v, w.w, acc.w);
            }
        }
        *(float4*)(out + ((size_t)g * B_ROWS + b) * DIM + d0) = acc;
    }
}

// ---------------- launch ------------------------------------------------------
extern "C" void kernel_launch(void* const* d_in, const int* in_sizes, int n_in,
                              void* d_out, int out_size)
{
    const float *x = nullptr, *Wenc = nullptr, *benc = nullptr,
                *Wdec = nullptr, *bdec = nullptr;
    for (int i = 0; i < n_in; i++) {
        const long long sz = (long long)in_sizes[i];
        const float* p = (const float*)d_in[i];
        if (sz == (long long)B_ROWS * DIM && !x) x = p;
        else if (sz == (long long)DIM * TDICT) { if (!Wenc) Wenc = p; else Wdec = p; }
        else if (sz == TDICT) benc = p;
        else if (sz == DIM) bdec = p;
    }
    (void)out_size;

    static bool attr_set = false;
    if (!attr_set) {
        cudaFuncSetAttribute(gemm_hmma_kernel,
                             cudaFuncAttributeMaxDynamicSharedMemorySize, GEMM_SMEM);
        attr_set = true;
    }

    prep_x_kernel<<<B_ROWS, 256>>>(x, bdec);
    prep_w_kernel<<<dim3(TDICT / 32, DIM / 32), 256>>>(Wenc);
    gemm_hmma_kernel<<<dim3(TDICT / GBN, B_ROWS / GBM), 256, GEMM_SMEM>>>(benc);
    topk_rescue_kernel<<<B_ROWS, 256>>>(benc);
    decode_kernel<<<B_ROWS, 256>>>(Wdec, bdec, (float*)d_out);
}

// round 9
// speedup vs baseline: 4.2086x; 1.0445x over previous
#include <cuda_runtime.h>
#include <cuda_bf16.h>
#include <cstdint>

#define B_ROWS 4096
#define DIM    1024
#define TDICT  32768
#define TOPK   64
#define THR    2.8f          // static screen threshold (64th val is >= ~3.8)
#define BAND   0.025f        // HMMA approx error guard band
#define NBLK   256           // column blocks (TDICT / 128)
#define SLOTS  16            // candidate slots per (row, colblock)
#define RSLOTS (NBLK * SLOTS)   // 4096 slots per row
#define SCAND  2048          // smem candidate list capacity

// ---------------- scratch (static device globals: allocation-guard safe) ----
__device__ float g_xcent[(size_t)B_ROWS * DIM];             // x - b_dec (fp32 rescue)
__device__ float g_Wt[(size_t)TDICT * DIM];                 // W_enc^T fp32 (rescue)
__device__ __nv_bfloat16 g_Abf[(size_t)B_ROWS * DIM];       // bf16(x - b_dec)
__device__ __nv_bfloat16 g_Bbf[(size_t)TDICT * DIM];        // bf16(W_enc^T)
__device__ unsigned long long g_cand[(size_t)B_ROWS * RSLOTS]; // 128 MB slotted cands
__device__ unsigned char g_cnt8[(size_t)B_ROWS * NBLK];     // per (row, colblk) count
__device__ float g_topv[B_ROWS * TOPK];
__device__ int   g_topi[B_ROWS * TOPK];

// ---------------- PTX helpers (compute_103 baseline only) -------------------
__device__ __forceinline__ uint32_t smem_u32(const void* p) {
    uint32_t a;
    asm("{ .reg .u64 t; cvta.to.shared.u64 t, %1; cvt.u32.u64 %0, t; }" : "=r"(a) : "l"(p));
    return a;
}
#define SWZ128(x) ((x) ^ (((x) >> 3) & 0x70))

__device__ __forceinline__ void cp_async16(uint32_t dst, const void* src) {
    asm volatile("cp.async.cg.shared.global [%0], [%1], 16;\n" :: "r"(dst), "l"(src) : "memory");
}
__device__ __forceinline__ void cp_commit() { asm volatile("cp.async.commit_group;" ::: "memory"); }
__device__ __forceinline__ void cp_wait0()  { asm volatile("cp.async.wait_group 0;" ::: "memory"); }

__device__ __forceinline__ void ldsm_x4(uint32_t* r, uint32_t addr) {
    asm volatile("ldmatrix.sync.aligned.m8n8.x4.shared.b16 {%0,%1,%2,%3}, [%4];"
                 : "=r"(r[0]), "=r"(r[1]), "=r"(r[2]), "=r"(r[3]) : "r"(addr));
}
__device__ __forceinline__ void mma16816(float* c, const uint32_t* a, const uint32_t* b) {
    asm volatile("mma.sync.aligned.m16n8k16.row.col.f32.bf16.bf16.f32 "
                 "{%0,%1,%2,%3}, {%4,%5,%6,%7}, {%8,%9}, {%0,%1,%2,%3};"
                 : "+f"(c[0]), "+f"(c[1]), "+f"(c[2]), "+f"(c[3])
                 : "r"(a[0]), "r"(a[1]), "r"(a[2]), "r"(a[3]), "r"(b[0]), "r"(b[1]));
}

__device__ __forceinline__ unsigned long long pack_cand(float v, int idx) {
    return ((unsigned long long)__float_as_uint(v) << 32)
           | (unsigned)(0xFFFFFFFFu - (unsigned)idx);
}

// ---------------- prep kernels ----------------------------------------------
__global__ __launch_bounds__(256)
void prep_x_kernel(const float* __restrict__ x, const float* __restrict__ bdec)
{
    const int b = blockIdx.x;
    for (int k = threadIdx.x; k < DIM; k += 256) {
        const float v = x[(size_t)b * DIM + k] - bdec[k];
        g_xcent[(size_t)b * DIM + k] = v;
        g_Abf[(size_t)b * DIM + k] = __float2bfloat16(v);
    }
}

__global__ __launch_bounds__(256)
void prep_w_kernel(const float* __restrict__ W)   // W_enc [1024, 32768]
{
    __shared__ float t[32][33];
    const int t0 = blockIdx.x * 32;   // feature base
    const int k0 = blockIdx.y * 32;   // k base
    const int tx = threadIdx.x & 31, ty = threadIdx.x >> 5;   // 32 x 8
    for (int r = ty; r < 32; r += 8)
        t[r][tx] = W[(size_t)(k0 + r) * TDICT + t0 + tx];
    __syncthreads();
    for (int r = ty; r < 32; r += 8) {
        const int feat = t0 + r;
        const int k = k0 + tx;
        const float v = t[tx][r];
        g_Wt[(size_t)feat * DIM + k] = v;
        g_Bbf[(size_t)feat * DIM + k] = __float2bfloat16(v);
    }
}

// ---------------- bf16 HMMA GEMM + fused slotted candidate screen -----------
// BM=256, BN=128, BK=64, 512 threads (16 warps as 4x4, warp tile 64x32).
#define GBM 256
#define GBN 128
#define GBK 64
#define GNK (DIM / GBK)        // 16
// smem: A stages 2x32KB at 0/32768, B stages 2x16KB at 65536/81920
#define GEMM_SMEM 98304

__device__ __forceinline__ void cp_tile(uint32_t As, uint32_t Bs,
                                        int blockRow, int blockCol, int kc, int tid)
{
#pragma unroll
    for (int i = 0; i < 4; i++) {                 // A: 256 rows x 8 chunks = 2048
        const int q = tid + i * 512;
        cp_async16(As + SWZ128((uint32_t)(q * 16)),
                   g_Abf + (size_t)(blockRow + (q >> 3)) * DIM + kc + (q & 7) * 8);
    }
#pragma unroll
    for (int i = 0; i < 2; i++) {                 // B: 128 rows x 8 chunks = 1024
        const int q = tid + i * 512;
        cp_async16(Bs + SWZ128((uint32_t)(q * 16)),
                   g_Bbf + (size_t)(blockCol + (q >> 3)) * DIM + kc + (q & 7) * 8);
    }
    cp_commit();
}

__global__ void __launch_bounds__(512)
gemm_hmma_kernel(const float* __restrict__ benc)
{
    extern __shared__ __align__(128) char smem[];
    const uint32_t sb = smem_u32(smem);
    const int tid  = threadIdx.x;
    const int lane = tid & 31, wid = tid >> 5;
    const int wm = wid & 3;            // 4 warps over M (64 rows each)
    const int wn = wid >> 2;           // 4 warps over N (32 cols each)
    const int blockRow = blockIdx.x * GBM;
    const int blockCol = blockIdx.y * GBN;
    const int colblk = blockIdx.y;

    const uint32_t As[2] = {sb, sb + 32768};
    const uint32_t Bs[2] = {sb + 65536, sb + 81920};

    float acc[4][4][4];
#pragma unroll
    for (int i = 0; i < 4; i++)
#pragma unroll
        for (int j = 0; j < 4; j++)
#pragma unroll
            for (int k = 0; k < 4; k++) acc[i][j][k] = 0.f;

    cp_tile(As[0], Bs[0], blockRow, blockCol, 0, tid);
    cp_wait0();
    __syncthreads();

    const int a_row = wm * 64 + (lane & 15);
    const int a_kb  = ((lane >> 4) & 1) * 16;
    const int b_row = wn * 32 + (lane & 7) + ((lane >> 4) & 1) * 8;
    const int b_kb  = ((lane >> 3) & 1) * 16;

#pragma unroll 1
    for (int kt = 0; kt < GNK; kt++) {
        const int buf = kt & 1;
        if (kt + 1 < GNK)
            cp_tile(As[buf ^ 1], Bs[buf ^ 1], blockRow, blockCol, (kt + 1) * GBK, tid);

#pragma unroll
        for (int ks = 0; ks < 4; ks++) {
            const int kb = ks * 32;
            uint32_t a[4][4];
#pragma unroll
            for (int mf = 0; mf < 4; mf++)
                ldsm_x4(a[mf], As[buf] + SWZ128((uint32_t)((a_row + mf * 16) * 128 + kb + a_kb)));
            uint32_t b[2][4];
#pragma unroll
            for (int nf = 0; nf < 2; nf++)
                ldsm_x4(b[nf], Bs[buf] + SWZ128((uint32_t)((b_row + nf * 16) * 128 + kb + b_kb)));
#pragma unroll
            for (int mf = 0; mf < 4; mf++)
#pragma unroll
                for (int n8 = 0; n8 < 4; n8++)
                    mma16816(acc[mf][n8], a[mf], &b[n8 >> 1][(n8 & 1) * 2]);
        }
        if (kt + 1 < GNK) { cp_wait0(); __syncthreads(); }
    }

    // ---- epilogue: stage candidates in smem (smem atomics only), then flush
    __syncthreads();                               // mainloop smem now reusable
    unsigned long long* slots = (unsigned long long*)smem;       // 256*16*8 = 32KB
    int* scnt = (int*)(smem + 32768);                            // 256*4 = 1KB
    for (int i = tid; i < GBM; i += 512) scnt[i] = 0;
    __syncthreads();

    const int gr = lane >> 2;
    const int gc = (lane & 3) * 2;
#pragma unroll
    for (int mf = 0; mf < 4; mf++) {
        const int lr0 = wm * 64 + mf * 16 + gr;
#pragma unroll
        for (int n8 = 0; n8 < 4; n8++) {
            const int n = blockCol + wn * 32 + n8 * 8 + gc;
            const float2 be = *(const float2*)(benc + n);
            const float v[4] = {acc[mf][n8][0] + be.x, acc[mf][n8][1] + be.y,
                                acc[mf][n8][2] + be.x, acc[mf][n8][3] + be.y};
            const int   rr[4] = {lr0, lr0, lr0 + 8, lr0 + 8};
            const int   cc[4] = {n, n + 1, n, n + 1};
#pragma unroll
            for (int q = 0; q < 4; q++) {
                if (v[q] > THR) {
                    const int p = atomicAdd(&scnt[rr[q]], 1);
                    if (p < SLOTS) slots[rr[q] * SLOTS + p] = pack_cand(v[q], cc[q]);
                }
            }
        }
    }
    __syncthreads();

    // flush: thread t handles local row t (256 rows, threads 256..511 idle)
    if (tid < GBM) {
        const int row = blockRow + tid;
        const int cnt = scnt[tid];
        const int w = (cnt > SLOTS) ? 255 : cnt;
        g_cnt8[(size_t)row * NBLK + colblk] = (unsigned char)w;
        unsigned long long* dst = g_cand + (size_t)row * RSLOTS + colblk * SLOTS;
        const int c = min(cnt, SLOTS);
        for (int k = 0; k < c; k++) dst[k] = slots[tid * SLOTS + k];
    }
}

// ---------------- top-k on candidates + exact fp32 rescue -------------------
__device__ __forceinline__ void bitonic_sort_desc(unsigned long long* a, int m, int tid)
{
    for (int size = 2; size <= m; size <<= 1) {
        for (int stride = size >> 1; stride > 0; stride >>= 1) {
            __syncthreads();
            for (int i = tid; i < m; i += 256) {
                const int j = i ^ stride;
                if (j > i) {
                    const unsigned long long x = a[i], y = a[j];
                    const bool desc = ((i & size) == 0);
                    if (desc ? (x < y) : (x > y)) { a[i] = y; a[j] = x; }
                }
            }
        }
    }
    __syncthreads();
}

__global__ __launch_bounds__(256)
void topk_rescue_kernel(const float* __restrict__ benc)
{
    __shared__ unsigned long long cand[SCAND];      // 16 KB
    __shared__ unsigned long long sel[1024];        // 8 KB
    __shared__ unsigned long long res[256];         // 2 KB
    __shared__ float xc[DIM];                       // 4 KB
    __shared__ unsigned int hist[1024];             // 4 KB
    __shared__ int cnt_s[NBLK];                     // 1 KB
    __shared__ int s_cut, s_scnt, s_rcnt, s_n, s_bad;

    const int b = blockIdx.x;
    const int tid = threadIdx.x;
    const int wid = tid >> 5, lid = tid & 31;

    for (int k = tid; k < DIM; k += 256) xc[k] = g_xcent[(size_t)b * DIM + k];
    for (int i = tid; i < 1024; i += 256) hist[i] = 0;
    if (tid == 0) { s_scnt = 0; s_rcnt = 0; s_n = 0; s_bad = 0; }
    // counts for this row (coalesced 256B)
    if (tid < NBLK) cnt_s[tid] = g_cnt8[(size_t)b * NBLK + tid];
    __syncthreads();
    if (tid < NBLK && cnt_s[tid] == 255) s_bad = 1;
    __syncthreads();

    if (!s_bad) {
        // gather valid slots (coalesced 32KB sweep, masked by counts)
        const unsigned long long* src = g_cand + (size_t)b * RSLOTS;
        for (int i = tid; i < RSLOTS; i += 256) {
            if ((i & (SLOTS - 1)) < cnt_s[i >> 4]) {
                const int p = atomicAdd(&s_n, 1);
                if (p < SCAND) cand[p] = src[i];
            }
        }
    }
    __syncthreads();

    int n = s_n;
    if (s_bad || n < 96 || n > SCAND) {
        // fallback (statistically unreachable): exact fp32 full-row recompute
        __syncthreads();
        if (tid == 0) s_n = 0;
        __syncthreads();
        const float4* xv4 = (const float4*)xc;
        for (int t = tid; t < TDICT; t += 256) {
            const float4* wrow = (const float4*)(g_Wt + (size_t)t * DIM);
            float s = 0.f;
            for (int j = 0; j < 256; j++) {
                const float4 w = wrow[j];
                const float4 xv = xv4[j];
                s = fmaf(xv.x, w.x, s); s = fmaf(xv.y, w.y, s);
                s = fmaf(xv.z, w.z, s); s = fmaf(xv.w, w.w, s);
            }
            s += benc[t];
            if (s > 2.5f) {
                const int p = atomicAdd(&s_n, 1);
                if (p < SCAND) cand[p] = pack_cand(s, t);
            }
        }
        __syncthreads();
        n = min(s_n, SCAND);
    }

    // histogram of top bits (monotonic for positive floats; bins <= 1023)
    for (int i = tid; i < n; i += 256)
        atomicAdd(&hist[(unsigned)(cand[i] >> 53)], 1u);
    __syncthreads();

    if (tid == 0) {
        unsigned cum = 0; int c = 0;
        for (int k = 1023; k >= 0; k--) { cum += hist[k]; if (cum >= TOPK) { c = k; break; } }
        s_cut = c;
    }
    __syncthreads();
    const unsigned cut = (unsigned)s_cut;

    // compact bins >= cut (superset of approx top-64)
    for (int i = tid; i < n; i += 256) {
        const unsigned long long c = cand[i];
        if ((unsigned)(c >> 53) >= cut) {
            const int p = atomicAdd(&s_scnt, 1);
            if (p < 1024) sel[p] = c;
        }
    }
    __syncthreads();

    unsigned long long* sarr;
    int sn;
    if (s_scnt <= 1024) { sarr = sel; sn = s_scnt; }
    else                { sarr = cand; sn = n; }
    int m = 64; while (m < sn) m <<= 1;
    for (int i = sn + tid; i < m; i += 256) sarr[i] = 0ull;
    bitonic_sort_desc(sarr, m, tid);

    const float v64 = __uint_as_float((unsigned)(sarr[63] >> 32));
    const float thr2 = v64 - BAND;

    // rescue set: all candidates with approx >= v64 - BAND (contains true top-64)
    for (int i = tid; i < n; i += 256) {
        const unsigned long long c = cand[i];
        if (__uint_as_float((unsigned)(c >> 32)) >= thr2) {
            const int p = atomicAdd(&s_rcnt, 1);
            if (p < 256) res[p] = c;
        }
    }
    __syncthreads();
    const int rn = min(s_rcnt, 256);

    // exact fp32 recompute for rescue set: one warp per candidate
    const float4* xv4 = (const float4*)xc;
#pragma unroll 1
    for (int e = wid; e < rn; e += 8) {
        const unsigned idx = 0xFFFFFFFFu - (unsigned)res[e];
        const float4* wrow = (const float4*)(g_Wt + (size_t)idx * DIM);
        float part = 0.f;
#pragma unroll
        for (int j = 0; j < 8; j++) {
            const float4 w = wrow[lid + j * 32];
            const float4 xv = xv4[lid + j * 32];
            part = fmaf(xv.x, w.x, part);
            part = fmaf(xv.y, w.y, part);
            part = fmaf(xv.z, w.z, part);
            part = fmaf(xv.w, w.w, part);
        }
#pragma unroll
        for (int o = 16; o > 0; o >>= 1)
            part += __shfl_xor_sync(0xFFFFFFFFu, part, o);
        if (lid == 0) {
            const float ex = fmaxf(part + benc[idx], 0.f);
            res[e] = pack_cand(ex, (int)idx);
        }
    }
    __syncthreads();

    int m2 = 64; while (m2 < rn) m2 <<= 1;
    for (int i = rn + tid; i < m2; i += 256) res[i] = 0ull;
    bitonic_sort_desc(res, m2, tid);

    if (tid < TOPK) {
        const unsigned long long k = res[tid];
        g_topv[b * TOPK + tid] = __uint_as_float((unsigned)(k >> 32));
        g_topi[b * TOPK + tid] = (int)(0xFFFFFFFFu - (unsigned)k);   // pad -> -1
    }
}

// ---------------- Nested group-wise sparse decode ----------------------------
__global__ __launch_bounds__(256)
void decode_kernel(const float* __restrict__ Wdec,
                   const float* __restrict__ bdec,
                   float* __restrict__ out)
{
    __shared__ float sv[TOPK];
    __shared__ int   si[TOPK];

    const int b = blockIdx.x;
    const int tid = threadIdx.x;
    if (tid < TOPK) {
        sv[tid] = g_topv[b * TOPK + tid];
        si[tid] = g_topi[b * TOPK + tid];
    }
    __syncthreads();

    const int d0 = tid * 4;
    float4 acc = *(const float4*)(bdec + d0);

    const int lo[3] = {0, 2048, 8192};
    const int hi[3] = {2048, 8192, 32768};

#pragma unroll 1
    for (int g = 0; g < 3; g++) {
#pragma unroll 1
        for (int e = 0; e < TOPK; e++) {
            const int idx = si[e];
            if (idx >= lo[g] && idx < hi[g]) {
                const float4 w = *(const float4*)(Wdec + (size_t)idx * DIM + d0);
                const float v = sv[e];
                acc.x = fmaf(v, w.x, acc.x);
                acc.y = fmaf(v, w.y, acc.y);
                acc.z = fmaf(v, w.z, acc.z);
                acc.w = fmaf(v, w.w, acc.w);
            }
        }
        *(float4*)(out + ((size_t)g * B_ROWS + b) * DIM + d0) = acc;
    }
}

// ---------------- launch ------------------------------------------------------
extern "C" void kernel_launch(void* const* d_in, const int* in_sizes, int n_in,
                              void* d_out, int out_size)
{
    const float *x = nullptr, *Wenc = nullptr, *benc = nullptr,
                *Wdec = nullptr, *bdec = nullptr;
    for (int i = 0; i < n_in; i++) {
        const long long sz = (long long)in_sizes[i];
        const float* p = (const float*)d_in[i];
        if (sz == (long long)B_ROWS * DIM && !x) x = p;
        else if (sz == (long long)DIM * TDICT) { if (!Wenc) Wenc = p; else Wdec = p; }
        else if (sz == TDICT) benc = p;
        else if (sz == DIM) bdec = p;
    }
    (void)out_size;

    static bool attr_set = false;
    if (!attr_set) {
        cudaFuncSetAttribute(gemm_hmma_kernel,
                             cudaFuncAttributeMaxDynamicSharedMemorySize, GEMM_SMEM);
        attr_set = true;
    }

    prep_x_kernel<<<B_ROWS, 256>>>(x, bdec);
    prep_w_kernel<<<dim3(TDICT / 32, DIM / 32), 256>>>(Wenc);
    gemm_hmma_kernel<<<dim3(B_ROWS / GBM, TDICT / GBN), 512, GEMM_SMEM>>>(benc);
    topk_rescue_kernel<<<B_ROWS, 256>>>(benc);
    decode_kernel<<<B_ROWS, 256>>>(Wdec, bdec, (float*)d_out);
}

// round 10
// speedup vs baseline: 4.8979x; 1.1638x over previous
#include <cuda_runtime.h>
#include <cuda_bf16.h>
#include <cstdint>

#define B_ROWS 4096
#define DIM    1024
#define TDICT  32768
#define TOPK   64
#define THR    2.8f          // static screen threshold (64th val is >= ~3.8)
#define RBAND  0.03f         // rescue guard band (covers 2x max HMMA error)
#define NBLK   256           // column blocks (TDICT / 128)
#define SLOTS  16            // candidate slots per (row, colblock)
#define RSLOTS (NBLK * SLOTS)   // 4096 slots per row
#define SCAND  2048          // smem candidate list capacity

// ---------------- scratch (static device globals: allocation-guard safe) ----
__device__ float g_xcent[(size_t)B_ROWS * DIM];             // x - b_dec (fp32 rescue)
__device__ float g_Wt[(size_t)TDICT * DIM];                 // W_enc^T fp32 (rescue)
__device__ __nv_bfloat16 g_Abf[(size_t)B_ROWS * DIM];       // bf16(x - b_dec)
__device__ __nv_bfloat16 g_Bbf[(size_t)TDICT * DIM];        // bf16(W_enc^T)
__device__ unsigned long long g_cand[(size_t)B_ROWS * RSLOTS]; // slotted candidates
__device__ unsigned char g_cnt8[(size_t)B_ROWS * NBLK];     // per (row, colblk) count
__device__ float g_topv[B_ROWS * TOPK];
__device__ int   g_topi[B_ROWS * TOPK];

// ---------------- PTX helpers (compute_103 baseline only) -------------------
__device__ __forceinline__ uint32_t smem_u32(const void* p) {
    uint32_t a;
    asm("{ .reg .u64 t; cvta.to.shared.u64 t, %1; cvt.u32.u64 %0, t; }" : "=r"(a) : "l"(p));
    return a;
}
#define SWZ128(x) ((x) ^ (((x) >> 3) & 0x70))

__device__ __forceinline__ void cp_async16(uint32_t dst, const void* src) {
    asm volatile("cp.async.cg.shared.global [%0], [%1], 16;\n" :: "r"(dst), "l"(src) : "memory");
}
__device__ __forceinline__ void cp_commit() { asm volatile("cp.async.commit_group;" ::: "memory"); }
__device__ __forceinline__ void cp_wait0()  { asm volatile("cp.async.wait_group 0;" ::: "memory"); }

__device__ __forceinline__ void ldsm_x4(uint32_t* r, uint32_t addr) {
    asm volatile("ldmatrix.sync.aligned.m8n8.x4.shared.b16 {%0,%1,%2,%3}, [%4];"
                 : "=r"(r[0]), "=r"(r[1]), "=r"(r[2]), "=r"(r[3]) : "r"(addr));
}
__device__ __forceinline__ void mma16816(float* c, const uint32_t* a, const uint32_t* b) {
    asm volatile("mma.sync.aligned.m16n8k16.row.col.f32.bf16.bf16.f32 "
                 "{%0,%1,%2,%3}, {%4,%5,%6,%7}, {%8,%9}, {%0,%1,%2,%3};"
                 : "+f"(c[0]), "+f"(c[1]), "+f"(c[2]), "+f"(c[3])
                 : "r"(a[0]), "r"(a[1]), "r"(a[2]), "r"(a[3]), "r"(b[0]), "r"(b[1]));
}

__device__ __forceinline__ unsigned long long pack_cand(float v, int idx) {
    return ((unsigned long long)__float_as_uint(v) << 32)
           | (unsigned)(0xFFFFFFFFu - (unsigned)idx);
}

__device__ __forceinline__ unsigned warp_incl_scan(unsigned v, int lid) {
#pragma unroll
    for (int o = 1; o < 32; o <<= 1) {
        const unsigned t = __shfl_up_sync(0xFFFFFFFFu, v, o);
        if (lid >= o) v += t;
    }
    return v;
}

// ---------------- prep kernels ----------------------------------------------
__global__ __launch_bounds__(256)
void prep_x_kernel(const float* __restrict__ x, const float* __restrict__ bdec)
{
    const int b = blockIdx.x;
    for (int k = threadIdx.x; k < DIM; k += 256) {
        const float v = x[(size_t)b * DIM + k] - bdec[k];
        g_xcent[(size_t)b * DIM + k] = v;
        g_Abf[(size_t)b * DIM + k] = __float2bfloat16(v);
    }
}

__global__ __launch_bounds__(256)
void prep_w_kernel(const float* __restrict__ W)   // W_enc [1024, 32768]
{
    __shared__ float t[32][33];
    const int t0 = blockIdx.x * 32;   // feature base
    const int k0 = blockIdx.y * 32;   // k base
    const int tx = threadIdx.x & 31, ty = threadIdx.x >> 5;   // 32 x 8
    for (int r = ty; r < 32; r += 8)
        t[r][tx] = W[(size_t)(k0 + r) * TDICT + t0 + tx];
    __syncthreads();
    for (int r = ty; r < 32; r += 8) {
        const int feat = t0 + r;
        const int k = k0 + tx;
        const float v = t[tx][r];
        g_Wt[(size_t)feat * DIM + k] = v;
        g_Bbf[(size_t)feat * DIM + k] = __float2bfloat16(v);
    }
}

// ---------------- bf16 HMMA GEMM + fused slotted candidate screen -----------
#define GBM 256
#define GBN 128
#define GBK 64
#define GNK (DIM / GBK)        // 16
#define GEMM_SMEM 98304

__device__ __forceinline__ void cp_tile(uint32_t As, uint32_t Bs,
                                        int blockRow, int blockCol, int kc, int tid)
{
#pragma unroll
    for (int i = 0; i < 4; i++) {
        const int q = tid + i * 512;
        cp_async16(As + SWZ128((uint32_t)(q * 16)),
                   g_Abf + (size_t)(blockRow + (q >> 3)) * DIM + kc + (q & 7) * 8);
    }
#pragma unroll
    for (int i = 0; i < 2; i++) {
        const int q = tid + i * 512;
        cp_async16(Bs + SWZ128((uint32_t)(q * 16)),
                   g_Bbf + (size_t)(blockCol + (q >> 3)) * DIM + kc + (q & 7) * 8);
    }
    cp_commit();
}

__global__ void __launch_bounds__(512)
gemm_hmma_kernel(const float* __restrict__ benc)
{
    extern __shared__ __align__(128) char smem[];
    const uint32_t sb = smem_u32(smem);
    const int tid  = threadIdx.x;
    const int lane = tid & 31, wid = tid >> 5;
    const int wm = wid & 3;
    const int wn = wid >> 2;
    const int blockRow = blockIdx.x * GBM;
    const int blockCol = blockIdx.y * GBN;
    const int colblk = blockIdx.y;

    const uint32_t As[2] = {sb, sb + 32768};
    const uint32_t Bs[2] = {sb + 65536, sb + 81920};

    float acc[4][4][4];
#pragma unroll
    for (int i = 0; i < 4; i++)
#pragma unroll
        for (int j = 0; j < 4; j++)
#pragma unroll
            for (int k = 0; k < 4; k++) acc[i][j][k] = 0.f;

    cp_tile(As[0], Bs[0], blockRow, blockCol, 0, tid);
    cp_wait0();
    __syncthreads();

    const int a_row = wm * 64 + (lane & 15);
    const int a_kb  = ((lane >> 4) & 1) * 16;
    const int b_row = wn * 32 + (lane & 7) + ((lane >> 4) & 1) * 8;
    const int b_kb  = ((lane >> 3) & 1) * 16;

#pragma unroll 1
    for (int kt = 0; kt < GNK; kt++) {
        const int buf = kt & 1;
        if (kt + 1 < GNK)
            cp_tile(As[buf ^ 1], Bs[buf ^ 1], blockRow, blockCol, (kt + 1) * GBK, tid);

#pragma unroll
        for (int ks = 0; ks < 4; ks++) {
            const int kb = ks * 32;
            uint32_t a[4][4];
#pragma unroll
            for (int mf = 0; mf < 4; mf++)
                ldsm_x4(a[mf], As[buf] + SWZ128((uint32_t)((a_row + mf * 16) * 128 + kb + a_kb)));
            uint32_t b[2][4];
#pragma unroll
            for (int nf = 0; nf < 2; nf++)
                ldsm_x4(b[nf], Bs[buf] + SWZ128((uint32_t)((b_row + nf * 16) * 128 + kb + b_kb)));
#pragma unroll
            for (int mf = 0; mf < 4; mf++)
#pragma unroll
                for (int n8 = 0; n8 < 4; n8++)
                    mma16816(acc[mf][n8], a[mf], &b[n8 >> 1][(n8 & 1) * 2]);
        }
        if (kt + 1 < GNK) { cp_wait0(); __syncthreads(); }
    }

    // ---- epilogue: stage candidates in smem, then slotted flush
    __syncthreads();
    unsigned long long* slots = (unsigned long long*)smem;       // 32KB
    int* scnt = (int*)(smem + 32768);                            // 1KB
    for (int i = tid; i < GBM; i += 512) scnt[i] = 0;
    __syncthreads();

    const int gr = lane >> 2;
    const int gc = (lane & 3) * 2;
#pragma unroll
    for (int mf = 0; mf < 4; mf++) {
        const int lr0 = wm * 64 + mf * 16 + gr;
#pragma unroll
        for (int n8 = 0; n8 < 4; n8++) {
            const int n = blockCol + wn * 32 + n8 * 8 + gc;
            const float2 be = *(const float2*)(benc + n);
            const float v[4] = {acc[mf][n8][0] + be.x, acc[mf][n8][1] + be.y,
                                acc[mf][n8][2] + be.x, acc[mf][n8][3] + be.y};
            const int   rr[4] = {lr0, lr0, lr0 + 8, lr0 + 8};
            const int   cc[4] = {n, n + 1, n, n + 1};
#pragma unroll
            for (int q = 0; q < 4; q++) {
                if (v[q] > THR) {
                    const int p = atomicAdd(&scnt[rr[q]], 1);
                    if (p < SLOTS) slots[rr[q] * SLOTS + p] = pack_cand(v[q], cc[q]);
                }
            }
        }
    }
    __syncthreads();

    if (tid < GBM) {
        const int row = blockRow + tid;
        const int cnt = scnt[tid];
        const int w = (cnt > SLOTS) ? 255 : cnt;
        g_cnt8[(size_t)row * NBLK + colblk] = (unsigned char)w;
        unsigned long long* dst = g_cand + (size_t)row * RSLOTS + colblk * SLOTS;
        const int c = min(cnt, SLOTS);
        for (int k = 0; k < c; k++) dst[k] = slots[tid * SLOTS + k];
    }
}

// ---------------- top-k: parallel histogram select + exact fp32 rescue ------
__device__ __forceinline__ void bitonic_sort_desc(unsigned long long* a, int m, int tid)
{
    for (int size = 2; size <= m; size <<= 1) {
        for (int stride = size >> 1; stride > 0; stride >>= 1) {
            __syncthreads();
            for (int i = tid; i < m; i += 256) {
                const int j = i ^ stride;
                if (j > i) {
                    const unsigned long long x = a[i], y = a[j];
                    const bool desc = ((i & size) == 0);
                    if (desc ? (x < y) : (x > y)) { a[i] = y; a[j] = x; }
                }
            }
        }
    }
    __syncthreads();
}

__global__ __launch_bounds__(256)
void topk_rescue_kernel(const float* __restrict__ benc)
{
    __shared__ unsigned long long cand[SCAND];      // 16 KB
    __shared__ unsigned long long res[256];         // 2 KB
    __shared__ float xc[DIM];                       // 4 KB
    __shared__ unsigned int hist[1024];             // 4 KB
    __shared__ unsigned int subhist[32];
    __shared__ unsigned int s_wsum[8];
    __shared__ int cnt_s[NBLK];                     // 1 KB
    __shared__ int s_cut, s_chi, s_sub, s_rcnt, s_n, s_bad;

    const int b = blockIdx.x;
    const int tid = threadIdx.x;
    const int wid = tid >> 5, lid = tid & 31;

    for (int k = tid; k < DIM; k += 256) xc[k] = g_xcent[(size_t)b * DIM + k];
    for (int i = tid; i < 1024; i += 256) hist[i] = 0;
    if (tid < 32) subhist[tid] = 0;
    if (tid == 0) { s_rcnt = 0; s_n = 0; s_bad = 0; }
    if (tid < NBLK) cnt_s[tid] = g_cnt8[(size_t)b * NBLK + tid];
    __syncthreads();
    if (tid < NBLK && cnt_s[tid] == 255) s_bad = 1;
    __syncthreads();

    if (!s_bad) {
        const unsigned long long* src = g_cand + (size_t)b * RSLOTS;
        for (int i = tid; i < RSLOTS; i += 256) {
            if ((i & (SLOTS - 1)) < cnt_s[i >> 4]) {
                const int p = atomicAdd(&s_n, 1);
                if (p < SCAND) cand[p] = src[i];
            }
        }
    }
    __syncthreads();

    int n = s_n;
    if (s_bad || n < 96 || n > SCAND) {
        // fallback (statistically unreachable): exact fp32 full-row recompute
        __syncthreads();
        if (tid == 0) s_n = 0;
        __syncthreads();
        const float4* xv4 = (const float4*)xc;
        for (int t = tid; t < TDICT; t += 256) {
            const float4* wrow = (const float4*)(g_Wt + (size_t)t * DIM);
            float s = 0.f;
            for (int j = 0; j < 256; j++) {
                const float4 w = wrow[j];
                const float4 xv = xv4[j];
                s = fmaf(xv.x, w.x, s); s = fmaf(xv.y, w.y, s);
                s = fmaf(xv.z, w.z, s); s = fmaf(xv.w, w.w, s);
            }
            s += benc[t];
            if (s > 2.5f) {
                const int p = atomicAdd(&s_n, 1);
                if (p < SCAND) cand[p] = pack_cand(s, t);
            }
        }
        __syncthreads();
        n = min(s_n, SCAND);
    }

    // 1024-bin histogram of top value bits (monotonic for positive floats)
    for (int i = tid; i < n; i += 256)
        atomicAdd(&hist[(unsigned)(cand[i] >> 53)], 1u);
    __syncthreads();

    // ---- parallel cut-bin selection: block-wide suffix counts
    {
        const int g0 = tid * 4;
        const unsigned pt = hist[g0] + hist[g0 + 1] + hist[g0 + 2] + hist[g0 + 3];
        unsigned incl = warp_incl_scan(pt, lid);
        if (lid == 31) s_wsum[wid] = incl;
        __syncthreads();
        if (wid == 0 && lid < 8) {
            unsigned v = s_wsum[lid];
#pragma unroll
            for (int o = 1; o < 8; o <<= 1) {
                const unsigned t = __shfl_up_sync(0xFFu, v, o);
                if (lid >= o) v += t;
            }
            s_wsum[lid] = v;
        }
        __syncthreads();
        const unsigned total = s_wsum[7];
        const unsigned incl_total = incl + (wid > 0 ? s_wsum[wid - 1] : 0u);
        const unsigned S_t = total - incl_total;   // count in groups above this one
        if (S_t < TOPK && S_t + pt >= TOPK) {
            unsigned cum = S_t;
#pragma unroll
            for (int bb = 3; bb >= 0; bb--) {
                const unsigned h = hist[g0 + bb];
                if (cum + h >= TOPK) { s_cut = g0 + bb; s_chi = (int)cum; break; }
                cum += h;
            }
        }
    }
    __syncthreads();
    const unsigned cut = (unsigned)s_cut;
    const int needed = TOPK - s_chi;               // in [1,64]

    // ---- sub-bin refine (5 more mantissa bits) inside the cut bin
    for (int i = tid; i < n; i += 256) {
        const unsigned long long c = cand[i];
        if ((unsigned)(c >> 53) == cut)
            atomicAdd(&subhist[(unsigned)(c >> 48) & 31u], 1u);
    }
    __syncthreads();
    if (tid < 32) {
        unsigned s = subhist[lid];
#pragma unroll
        for (int o = 1; o < 32; o <<= 1) {
            const unsigned v = __shfl_down_sync(0xFFFFFFFFu, s, o);
            if (lid + o < 32) s += v;
        }
        const unsigned Snext = __shfl_down_sync(0xFFFFFFFFu, s, 1);
        if (s >= (unsigned)needed && (lid == 31 || Snext < (unsigned)needed))
            s_sub = lid;
    }
    __syncthreads();

    // v64 lower bound from (cut, sub) bin edge; rescue threshold
    const unsigned v64lb_bits = (cut << 21) | ((unsigned)s_sub << 16);
    const float thr2 = __uint_as_float(v64lb_bits) - RBAND;

    // ---- rescue set: all candidates with approx >= thr2 (superset of top-64)
    for (int i = tid; i < n; i += 256) {
        const unsigned long long c = cand[i];
        if (__uint_as_float((unsigned)(c >> 32)) >= thr2) {
            const int p = atomicAdd(&s_rcnt, 1);
            if (p < 256) res[p] = c;
        }
    }
    __syncthreads();
    const int rn = min(s_rcnt, 256);

    // ---- exact fp32 recompute, 2 candidates per warp in flight
    const float4* xv4 = (const float4*)xc;
#pragma unroll 1
    for (int e = wid; e < rn; e += 16) {
        const int e1 = e + 8;
        const bool has1 = (e1 < rn);
        const unsigned idx0 = 0xFFFFFFFFu - (unsigned)res[e];
        const unsigned idx1 = has1 ? (0xFFFFFFFFu - (unsigned)res[e1]) : idx0;
        const float4* w0 = (const float4*)(g_Wt + (size_t)idx0 * DIM);
        const float4* w1 = (const float4*)(g_Wt + (size_t)idx1 * DIM);
        float p0 = 0.f, p1 = 0.f;
#pragma unroll
        for (int h = 0; h < 2; h++) {
            float4 a0[4], a1[4];
#pragma unroll
            for (int j = 0; j < 4; j++) {
                a0[j] = w0[lid + (h * 4 + j) * 32];
                a1[j] = w1[lid + (h * 4 + j) * 32];
            }
#pragma unroll
            for (int j = 0; j < 4; j++) {
                const float4 xv = xv4[lid + (h * 4 + j) * 32];
                p0 = fmaf(xv.x, a0[j].x, p0); p0 = fmaf(xv.y, a0[j].y, p0);
                p0 = fmaf(xv.z, a0[j].z, p0); p0 = fmaf(xv.w, a0[j].w, p0);
                p1 = fmaf(xv.x, a1[j].x, p1); p1 = fmaf(xv.y, a1[j].y, p1);
                p1 = fmaf(xv.z, a1[j].z, p1); p1 = fmaf(xv.w, a1[j].w, p1);
            }
        }
#pragma unroll
        for (int o = 16; o > 0; o >>= 1) {
            p0 += __shfl_xor_sync(0xFFFFFFFFu, p0, o);
            p1 += __shfl_xor_sync(0xFFFFFFFFu, p1, o);
        }
        if (lid == 0) {
            res[e] = pack_cand(fmaxf(p0 + benc[idx0], 0.f), (int)idx0);
            if (has1) res[e1] = pack_cand(fmaxf(p1 + benc[idx1], 0.f), (int)idx1);
        }
    }
    __syncthreads();

    int m2 = 64; while (m2 < rn) m2 <<= 1;
    for (int i = rn + tid; i < m2; i += 256) res[i] = 0ull;
    bitonic_sort_desc(res, m2, tid);

    if (tid < TOPK) {
        const unsigned long long k = res[tid];
        g_topv[b * TOPK + tid] = __uint_as_float((unsigned)(k >> 32));
        g_topi[b * TOPK + tid] = (int)(0xFFFFFFFFu - (unsigned)k);   // pad -> -1
    }
}

// ---------------- Nested group-wise sparse decode (single pass, MLP) --------
__global__ __launch_bounds__(256)
void decode_kernel(const float* __restrict__ Wdec,
                   const float* __restrict__ bdec,
                   float* __restrict__ out)
{
    __shared__ float sv[TOPK];
    __shared__ int   si[TOPK];

    const int b = blockIdx.x;
    const int tid = threadIdx.x;
    if (tid < TOPK) {
        sv[tid] = g_topv[b * TOPK + tid];
        si[tid] = g_topi[b * TOPK + tid];
    }
    __syncthreads();

    const int d0 = tid * 4;
    float4 s0 = {0.f, 0.f, 0.f, 0.f}, s1 = s0, s2 = s0;

#pragma unroll 4
    for (int e = 0; e < TOPK; e++) {
        const int idx = si[e];
        const int ic = (idx >= 0) ? idx : 0;
        const float v = (idx >= 0) ? sv[e] : 0.f;
        const float4 w = *(const float4*)(Wdec + (size_t)ic * DIM + d0);
        if (idx < 2048) {
            s0.x = fmaf(v, w.x, s0.x); s0.y = fmaf(v, w.y, s0.y);
            s0.z = fmaf(v, w.z, s0.z); s0.w = fmaf(v, w.w, s0.w);
        } else if (idx < 8192) {
            s1.x = fmaf(v, w.x, s1.x); s1.y = fmaf(v, w.y, s1.y);
            s1.z = fmaf(v, w.z, s1.z); s1.w = fmaf(v, w.w, s1.w);
        } else {
            s2.x = fmaf(v, w.x, s2.x); s2.y = fmaf(v, w.y, s2.y);
            s2.z = fmaf(v, w.z, s2.z); s2.w = fmaf(v, w.w, s2.w);
        }
    }

    const float4 bd = *(const float4*)(bdec + d0);
    float4 o0, o1, o2;
    o0.x = bd.x + s0.x; o0.y = bd.y + s0.y; o0.z = bd.z + s0.z; o0.w = bd.w + s0.w;
    o1.x = o0.x + s1.x; o1.y = o0.y + s1.y; o1.z = o0.z + s1.z; o1.w = o0.w + s1.w;
    o2.x = o1.x + s2.x; o2.y = o1.y + s2.y; o2.z = o1.z + s2.z; o2.w = o1.w + s2.w;

    *(float4*)(out + ((size_t)0 * B_ROWS + b) * DIM + d0) = o0;
    *(float4*)(out + ((size_t)1 * B_ROWS + b) * DIM + d0) = o1;
    *(float4*)(out + ((size_t)2 * B_ROWS + b) * DIM + d0) = o2;
}

// ---------------- launch ------------------------------------------------------
extern "C" void kernel_launch(void* const* d_in, const int* in_sizes, int n_in,
                              void* d_out, int out_size)
{
    const float *x = nullptr, *Wenc = nullptr, *benc = nullptr,
                *Wdec = nullptr, *bdec = nullptr;
    for (int i = 0; i < n_in; i++) {
        const long long sz = (long long)in_sizes[i];
        const float* p = (const float*)d_in[i];
        if (sz == (long long)B_ROWS * DIM && !x) x = p;
        else if (sz == (long long)DIM * TDICT) { if (!Wenc) Wenc = p; else Wdec = p; }
        else if (sz == TDICT) benc = p;
        else if (sz == DIM) bdec = p;
    }
    (void)out_size;

    static bool attr_set = false;
    if (!attr_set) {
        cudaFuncSetAttribute(gemm_hmma_kernel,
                             cudaFuncAttributeMaxDynamicSharedMemorySize, GEMM_SMEM);
        attr_set = true;
    }

    prep_x_kernel<<<B_ROWS, 256>>>(x, bdec);
    prep_w_kernel<<<dim3(TDICT / 32, DIM / 32), 256>>>(Wenc);
    gemm_hmma_kernel<<<dim3(B_ROWS / GBM, TDICT / GBN), 512, GEMM_SMEM>>>(benc);
    topk_rescue_kernel<<<B_ROWS, 256>>>(benc);
    decode_kernel<<<B_ROWS, 256>>>(Wdec, bdec, (float*)d_out);
}

// round 11
// speedup vs baseline: 5.2733x; 1.0766x over previous
#include <cuda_runtime.h>
#include <cuda_fp16.h>
#include <cstdint>

#define B_ROWS 4096
#define DIM    1024
#define TDICT  32768
#define TOPK   64
#define THR    2.8f          // static screen threshold (64th val is >= ~3.8)
#define EPS    4e-3f         // fp16-screen error bound (~7 sigma)
#define NBLK   256           // column blocks (TDICT / 128)
#define SLOTS  16            // candidate slots per (row, colblock)
#define RSLOTS (NBLK * SLOTS)   // 4096 slots per row
#define SCAND  2048          // smem candidate list capacity

// ---------------- scratch (static device globals: allocation-guard safe) ----
__device__ float g_xcent[(size_t)B_ROWS * DIM];             // x - b_dec (fp32 rescue)
__device__ float g_Wt[(size_t)TDICT * DIM];                 // W_enc^T fp32 (rescue)
__device__ __half g_Ah[(size_t)B_ROWS * DIM];               // fp16(x - b_dec)
__device__ __half g_Bh[(size_t)TDICT * DIM];                // fp16(W_enc^T)
__device__ unsigned long long g_cand[(size_t)B_ROWS * RSLOTS]; // slotted candidates
__device__ unsigned char g_cnt8[(size_t)B_ROWS * NBLK];     // per (row, colblk) count
__device__ float g_topv[B_ROWS * TOPK];
__device__ int   g_topi[B_ROWS * TOPK];

// ---------------- PTX helpers (compute_103 baseline only) -------------------
__device__ __forceinline__ uint32_t smem_u32(const void* p) {
    uint32_t a;
    asm("{ .reg .u64 t; cvta.to.shared.u64 t, %1; cvt.u32.u64 %0, t; }" : "=r"(a) : "l"(p));
    return a;
}
#define SWZ128(x) ((x) ^ (((x) >> 3) & 0x70))

__device__ __forceinline__ void cp_async16(uint32_t dst, const void* src) {
    asm volatile("cp.async.cg.shared.global [%0], [%1], 16;\n" :: "r"(dst), "l"(src) : "memory");
}
__device__ __forceinline__ void cp_commit() { asm volatile("cp.async.commit_group;" ::: "memory"); }
__device__ __forceinline__ void cp_wait0()  { asm volatile("cp.async.wait_group 0;" ::: "memory"); }

__device__ __forceinline__ void ldsm_x4(uint32_t* r, uint32_t addr) {
    asm volatile("ldmatrix.sync.aligned.m8n8.x4.shared.b16 {%0,%1,%2,%3}, [%4];"
                 : "=r"(r[0]), "=r"(r[1]), "=r"(r[2]), "=r"(r[3]) : "r"(addr));
}
__device__ __forceinline__ void mma16816(float* c, const uint32_t* a, const uint32_t* b) {
    asm volatile("mma.sync.aligned.m16n8k16.row.col.f32.f16.f16.f32 "
                 "{%0,%1,%2,%3}, {%4,%5,%6,%7}, {%8,%9}, {%0,%1,%2,%3};"
                 : "+f"(c[0]), "+f"(c[1]), "+f"(c[2]), "+f"(c[3])
                 : "r"(a[0]), "r"(a[1]), "r"(a[2]), "r"(a[3]), "r"(b[0]), "r"(b[1]));
}

__device__ __forceinline__ unsigned long long pack_cand(float v, int idx) {
    return ((unsigned long long)__float_as_uint(v) << 32)
           | (unsigned)(0xFFFFFFFFu - (unsigned)idx);
}

__device__ __forceinline__ unsigned warp_incl_scan(unsigned v, int lid) {
#pragma unroll
    for (int o = 1; o < 32; o <<= 1) {
        const unsigned t = __shfl_up_sync(0xFFFFFFFFu, v, o);
        if (lid >= o) v += t;
    }
    return v;
}

// ---------------- prep kernels ----------------------------------------------
__global__ __launch_bounds__(256)
void prep_x_kernel(const float* __restrict__ x, const float* __restrict__ bdec)
{
    const int b = blockIdx.x;
    for (int k = threadIdx.x; k < DIM; k += 256) {
        const float v = x[(size_t)b * DIM + k] - bdec[k];
        g_xcent[(size_t)b * DIM + k] = v;
        g_Ah[(size_t)b * DIM + k] = __float2half(v);
    }
}

__global__ __launch_bounds__(256)
void prep_w_kernel(const float* __restrict__ W)   // W_enc [1024, 32768]
{
    __shared__ float t[32][33];
    const int t0 = blockIdx.x * 32;   // feature base
    const int k0 = blockIdx.y * 32;   // k base
    const int tx = threadIdx.x & 31, ty = threadIdx.x >> 5;   // 32 x 8
    for (int r = ty; r < 32; r += 8)
        t[r][tx] = W[(size_t)(k0 + r) * TDICT + t0 + tx];
    __syncthreads();
    for (int r = ty; r < 32; r += 8) {
        const int feat = t0 + r;
        const int k = k0 + tx;
        const float v = t[tx][r];
        g_Wt[(size_t)feat * DIM + k] = v;
        g_Bh[(size_t)feat * DIM + k] = __float2half(v);
    }
}

// ---------------- fp16 HMMA GEMM + fused slotted candidate screen -----------
#define GBM 256
#define GBN 128
#define GBK 64
#define GNK (DIM / GBK)        // 16
#define GEMM_SMEM 98304

__device__ __forceinline__ void cp_tile(uint32_t As, uint32_t Bs,
                                        int blockRow, int blockCol, int kc, int tid)
{
#pragma unroll
    for (int i = 0; i < 4; i++) {
        const int q = tid + i * 512;
        cp_async16(As + SWZ128((uint32_t)(q * 16)),
                   g_Ah + (size_t)(blockRow + (q >> 3)) * DIM + kc + (q & 7) * 8);
    }
#pragma unroll
    for (int i = 0; i < 2; i++) {
        const int q = tid + i * 512;
        cp_async16(Bs + SWZ128((uint32_t)(q * 16)),
                   g_Bh + (size_t)(blockCol + (q >> 3)) * DIM + kc + (q & 7) * 8);
    }
    cp_commit();
}

__global__ void __launch_bounds__(512)
gemm_hmma_kernel(const float* __restrict__ benc)
{
    extern __shared__ __align__(128) char smem[];
    const uint32_t sb = smem_u32(smem);
    const int tid  = threadIdx.x;
    const int lane = tid & 31, wid = tid >> 5;
    const int wm = wid & 3;
    const int wn = wid >> 2;
    const int blockRow = blockIdx.x * GBM;
    const int blockCol = blockIdx.y * GBN;
    const int colblk = blockIdx.y;

    const uint32_t As[2] = {sb, sb + 32768};
    const uint32_t Bs[2] = {sb + 65536, sb + 81920};

    float acc[4][4][4];
#pragma unroll
    for (int i = 0; i < 4; i++)
#pragma unroll
        for (int j = 0; j < 4; j++)
#pragma unroll
            for (int k = 0; k < 4; k++) acc[i][j][k] = 0.f;

    cp_tile(As[0], Bs[0], blockRow, blockCol, 0, tid);
    cp_wait0();
    __syncthreads();

    const int a_row = wm * 64 + (lane & 15);
    const int a_kb  = ((lane >> 4) & 1) * 16;
    const int b_row = wn * 32 + (lane & 7) + ((lane >> 4) & 1) * 8;
    const int b_kb  = ((lane >> 3) & 1) * 16;

#pragma unroll 1
    for (int kt = 0; kt < GNK; kt++) {
        const int buf = kt & 1;
        if (kt + 1 < GNK)
            cp_tile(As[buf ^ 1], Bs[buf ^ 1], blockRow, blockCol, (kt + 1) * GBK, tid);

#pragma unroll
        for (int ks = 0; ks < 4; ks++) {
            const int kb = ks * 32;
            uint32_t a[4][4];
#pragma unroll
            for (int mf = 0; mf < 4; mf++)
                ldsm_x4(a[mf], As[buf] + SWZ128((uint32_t)((a_row + mf * 16) * 128 + kb + a_kb)));
            uint32_t b[2][4];
#pragma unroll
            for (int nf = 0; nf < 2; nf++)
                ldsm_x4(b[nf], Bs[buf] + SWZ128((uint32_t)((b_row + nf * 16) * 128 + kb + b_kb)));
#pragma unroll
            for (int mf = 0; mf < 4; mf++)
#pragma unroll
                for (int n8 = 0; n8 < 4; n8++)
                    mma16816(acc[mf][n8], a[mf], &b[n8 >> 1][(n8 & 1) * 2]);
        }
        if (kt + 1 < GNK) { cp_wait0(); __syncthreads(); }
    }

    // ---- epilogue: stage candidates in smem, then slotted flush
    __syncthreads();
    unsigned long long* slots = (unsigned long long*)smem;       // 32KB
    int* scnt = (int*)(smem + 32768);                            // 1KB
    for (int i = tid; i < GBM; i += 512) scnt[i] = 0;
    __syncthreads();

    const int gr = lane >> 2;
    const int gc = (lane & 3) * 2;
#pragma unroll
    for (int mf = 0; mf < 4; mf++) {
        const int lr0 = wm * 64 + mf * 16 + gr;
#pragma unroll
        for (int n8 = 0; n8 < 4; n8++) {
            const int n = blockCol + wn * 32 + n8 * 8 + gc;
            const float2 be = *(const float2*)(benc + n);
            const float v[4] = {acc[mf][n8][0] + be.x, acc[mf][n8][1] + be.y,
                                acc[mf][n8][2] + be.x, acc[mf][n8][3] + be.y};
            const int   rr[4] = {lr0, lr0, lr0 + 8, lr0 + 8};
            const int   cc[4] = {n, n + 1, n, n + 1};
#pragma unroll
            for (int q = 0; q < 4; q++) {
                if (v[q] > THR) {
                    const int p = atomicAdd(&scnt[rr[q]], 1);
                    if (p < SLOTS) slots[rr[q] * SLOTS + p] = pack_cand(v[q], cc[q]);
                }
            }
        }
    }
    __syncthreads();

    if (tid < GBM) {
        const int row = blockRow + tid;
        const int cnt = scnt[tid];
        const int w = (cnt > SLOTS) ? 255 : cnt;
        g_cnt8[(size_t)row * NBLK + colblk] = (unsigned char)w;
        unsigned long long* dst = g_cand + (size_t)row * RSLOTS + colblk * SLOTS;
        const int c = min(cnt, SLOTS);
        for (int k = 0; k < c; k++) dst[k] = slots[tid * SLOTS + k];
    }
}

// ---------------- top-k: certainty-band selection + minimal exact rescue ----
__device__ __forceinline__ void bitonic_sort_desc(unsigned long long* a, int m, int tid)
{
    for (int size = 2; size <= m; size <<= 1) {
        for (int stride = size >> 1; stride > 0; stride >>= 1) {
            __syncthreads();
            for (int i = tid; i < m; i += 256) {
                const int j = i ^ stride;
                if (j > i) {
                    const unsigned long long x = a[i], y = a[j];
                    const bool desc = ((i & size) == 0);
                    if (desc ? (x < y) : (x > y)) { a[i] = y; a[j] = x; }
                }
            }
        }
    }
    __syncthreads();
}

__global__ __launch_bounds__(256)
void topk_rescue_kernel(const float* __restrict__ benc)
{
    __shared__ unsigned long long cand[SCAND];      // 16 KB
    __shared__ unsigned long long res[256];         // 2 KB (band superset, sorted)
    __shared__ unsigned long long res2[128];        // 1 KB (rescued, exact)
    __shared__ float xc[DIM];                       // 4 KB
    __shared__ unsigned int hist[1024];             // 4 KB
    __shared__ unsigned int subhist[32];
    __shared__ unsigned int s_wsum[8];
    __shared__ int cnt_s[NBLK];                     // 1 KB
    __shared__ int s_cut, s_chi, s_sub, s_rcnt, s_acnt, s_n, s_bad;

    const int b = blockIdx.x;
    const int tid = threadIdx.x;
    const int wid = tid >> 5, lid = tid & 31;

    for (int k = tid; k < DIM; k += 256) xc[k] = g_xcent[(size_t)b * DIM + k];
    for (int i = tid; i < 1024; i += 256) hist[i] = 0;
    if (tid < 32) subhist[tid] = 0;
    if (tid == 0) { s_rcnt = 0; s_acnt = 0; s_n = 0; s_bad = 0; }
    if (tid < NBLK) cnt_s[tid] = g_cnt8[(size_t)b * NBLK + tid];
    __syncthreads();
    if (tid < NBLK && cnt_s[tid] == 255) s_bad = 1;
    __syncthreads();

    if (!s_bad) {
        const unsigned long long* src = g_cand + (size_t)b * RSLOTS;
        for (int i = tid; i < RSLOTS; i += 256) {
            if ((i & (SLOTS - 1)) < cnt_s[i >> 4]) {
                const int p = atomicAdd(&s_n, 1);
                if (p < SCAND) cand[p] = src[i];
            }
        }
    }
    __syncthreads();

    int n = s_n;
    if (s_bad || n < 96 || n > SCAND) {
        // fallback (statistically unreachable): exact fp32 full-row recompute
        __syncthreads();
        if (tid == 0) s_n = 0;
        __syncthreads();
        const float4* xv4 = (const float4*)xc;
        for (int t = tid; t < TDICT; t += 256) {
            const float4* wrow = (const float4*)(g_Wt + (size_t)t * DIM);
            float s = 0.f;
            for (int j = 0; j < 256; j++) {
                const float4 w = wrow[j];
                const float4 xv = xv4[j];
                s = fmaf(xv.x, w.x, s); s = fmaf(xv.y, w.y, s);
                s = fmaf(xv.z, w.z, s); s = fmaf(xv.w, w.w, s);
            }
            s += benc[t];
            if (s > 2.5f) {
                const int p = atomicAdd(&s_n, 1);
                if (p < SCAND) cand[p] = pack_cand(s, t);
            }
        }
        __syncthreads();
        n = min(s_n, SCAND);
    }

    // 1024-bin histogram of top value bits (monotonic for positive floats)
    for (int i = tid; i < n; i += 256)
        atomicAdd(&hist[(unsigned)(cand[i] >> 53)], 1u);
    __syncthreads();

    // ---- parallel cut-bin selection: block-wide suffix counts
    {
        const int g0 = tid * 4;
        const unsigned pt = hist[g0] + hist[g0 + 1] + hist[g0 + 2] + hist[g0 + 3];
        unsigned incl = warp_incl_scan(pt, lid);
        if (lid == 31) s_wsum[wid] = incl;
        __syncthreads();
        if (wid == 0 && lid < 8) {
            unsigned v = s_wsum[lid];
#pragma unroll
            for (int o = 1; o < 8; o <<= 1) {
                const unsigned t = __shfl_up_sync(0xFFu, v, o);
                if (lid >= o) v += t;
            }
            s_wsum[lid] = v;
        }
        __syncthreads();
        const unsigned total = s_wsum[7];
        const unsigned incl_total = incl + (wid > 0 ? s_wsum[wid - 1] : 0u);
        const unsigned S_t = total - incl_total;
        if (S_t < TOPK && S_t + pt >= TOPK) {
            unsigned cum = S_t;
#pragma unroll
            for (int bb = 3; bb >= 0; bb--) {
                const unsigned h = hist[g0 + bb];
                if (cum + h >= TOPK) { s_cut = g0 + bb; s_chi = (int)cum; break; }
                cum += h;
            }
        }
    }
    __syncthreads();
    const unsigned cut = (unsigned)s_cut;
    const int needed = TOPK - s_chi;               // in [1,64]

    // ---- sub-bin refine (5 more mantissa bits) inside the cut bin
    for (int i = tid; i < n; i += 256) {
        const unsigned long long c = cand[i];
        if ((unsigned)(c >> 53) == cut)
            atomicAdd(&subhist[(unsigned)(c >> 48) & 31u], 1u);
    }
    __syncthreads();
    if (tid < 32) {
        unsigned s = subhist[lid];
#pragma unroll
        for (int o = 1; o < 32; o <<= 1) {
            const unsigned v = __shfl_down_sync(0xFFFFFFFFu, s, o);
            if (lid + o < 32) s += v;
        }
        const unsigned Snext = __shfl_down_sync(0xFFFFFFFFu, s, 1);
        if (s >= (unsigned)needed && (lid == 31 || Snext < (unsigned)needed))
            s_sub = lid;
    }
    __syncthreads();

    // v64 bracket [lb, ub) from (cut, sub) bin edges
    const unsigned v64lb_bits = (cut << 21) | ((unsigned)s_sub << 16);
    const unsigned v64ub_bits = v64lb_bits + (1u << 16);
    const float thrB = __uint_as_float(v64lb_bits) - 2.f * EPS;  // superset bound
    const float thrA = __uint_as_float(v64ub_bits) + 2.f * EPS;  // certainty bound

    // ---- collect B = {approx >= thrB}; count A = {approx >= thrA}
    for (int i = tid; i < n; i += 256) {
        const unsigned long long c = cand[i];
        const float av = __uint_as_float((unsigned)(c >> 32));
        if (av >= thrB) {
            const int p = atomicAdd(&s_rcnt, 1);
            if (p < 256) res[p] = c;
            if (av >= thrA) atomicAdd(&s_acnt, 1);
        }
    }
    __syncthreads();
    const int rn = min(s_rcnt, 256);
    const int nA = min(s_acnt, TOPK);     // provably subset of exact top-64
    const int need = TOPK - nA;

    // sort B desc by approx: first nA entries are the certain set
    int m = 64; while (m < rn) m <<= 1;
    for (int i = rn + tid; i < m; i += 256) res[i] = 0ull;
    bitonic_sort_desc(res, m, tid);

    // ---- exact fp32 recompute only for band members res[nA..rn)
    const int bn = min(rn - nA, 128);
    const float4* xv4 = (const float4*)xc;
#pragma unroll 1
    for (int e = wid; e < bn; e += 8) {
        const unsigned idx = 0xFFFFFFFFu - (unsigned)res[nA + e];
        const float4* wrow = (const float4*)(g_Wt + (size_t)idx * DIM);
        float part = 0.f;
#pragma unroll
        for (int j = 0; j < 8; j++) {
            const float4 w = wrow[lid + j * 32];
            const float4 xv = xv4[lid + j * 32];
            part = fmaf(xv.x, w.x, part);
            part = fmaf(xv.y, w.y, part);
            part = fmaf(xv.z, w.z, part);
            part = fmaf(xv.w, w.w, part);
        }
#pragma unroll
        for (int o = 16; o > 0; o >>= 1)
            part += __shfl_xor_sync(0xFFFFFFFFu, part, o);
        if (lid == 0)
            res2[e] = pack_cand(fmaxf(part + benc[idx], 0.f), (int)idx);
    }
    __syncthreads();

    // sort rescued by exact value desc; take the first `need`
    int m2 = 1; while (m2 < bn) m2 <<= 1;
    if (m2 < 2) m2 = 2;
    for (int i = bn + tid; i < m2; i += 256) res2[i] = 0ull;
    bitonic_sort_desc(res2, m2, tid);

    // ---- final 64 = certain set (approx values) + top-`need` rescued (exact)
    if (tid < TOPK) {
        const unsigned long long k = (tid < nA) ? res[tid] : res2[tid - nA];
        g_topv[b * TOPK + tid] = __uint_as_float((unsigned)(k >> 32));
        g_topi[b * TOPK + tid] = (int)(0xFFFFFFFFu - (unsigned)k);
    }
}

// ---------------- Nested group-wise sparse decode (single pass) -------------
__global__ __launch_bounds__(256)
void decode_kernel(const float* __restrict__ Wdec,
                   const float* __restrict__ bdec,
                   float* __restrict__ out)
{
    __shared__ float sv[TOPK];
    __shared__ int   si[TOPK];

    const int b = blockIdx.x;
    const int tid = threadIdx.x;
    if (tid < TOPK) {
        sv[tid] = g_topv[b * TOPK + tid];
        si[tid] = g_topi[b * TOPK + tid];
    }
    __syncthreads();

    const int d0 = tid * 4;
    float4 s0 = {0.f, 0.f, 0.f, 0.f}, s1 = s0, s2 = s0;

#pragma unroll 4
    for (int e = 0; e < TOPK; e++) {
        const int idx = si[e];
        const int ic = (idx >= 0) ? idx : 0;
        const float v = (idx >= 0) ? sv[e] : 0.f;
        const float4 w = *(const float4*)(Wdec + (size_t)ic * DIM + d0);
        if (idx < 2048) {
            s0.x = fmaf(v, w.x, s0.x); s0.y = fmaf(v, w.y, s0.y);
            s0.z = fmaf(v, w.z, s0.z); s0.w = fmaf(v, w.w, s0.w);
        } else if (idx < 8192) {
            s1.x = fmaf(v, w.x, s1.x); s1.y = fmaf(v, w.y, s1.y);
            s1.z = fmaf(v, w.z, s1.z); s1.w = fmaf(v, w.w, s1.w);
        } else {
            s2.x = fmaf(v, w.x, s2.x); s2.y = fmaf(v, w.y, s2.y);
            s2.z = fmaf(v, w.z, s2.z); s2.w = fmaf(v, w.w, s2.w);
        }
    }

    const float4 bd = *(const float4*)(bdec + d0);
    float4 o0, o1, o2;
    o0.x = bd.x + s0.x; o0.y = bd.y + s0.y; o0.z = bd.z + s0.z; o0.w = bd.w + s0.w;
    o1.x = o0.x + s1.x; o1.y = o0.y + s1.y; o1.z = o0.z + s1.z; o1.w = o0.w + s1.w;
    o2.x = o1.x + s2.x; o2.y = o1.y + s2.y; o2.z = o1.z + s2.z; o2.w = o1.w + s2.w;

    *(float4*)(out + ((size_t)0 * B_ROWS + b) * DIM + d0) = o0;
    *(float4*)(out + ((size_t)1 * B_ROWS + b) * DIM + d0) = o1;
    *(float4*)(out + ((size_t)2 * B_ROWS + b) * DIM + d0) = o2;
}

// ---------------- launch ------------------------------------------------------
extern "C" void kernel_launch(void* const* d_in, const int* in_sizes, int n_in,
                              void* d_out, int out_size)
{
    const float *x = nullptr, *Wenc = nullptr, *benc = nullptr,
                *Wdec = nullptr, *bdec = nullptr;
    for (int i = 0; i < n_in; i++) {
        const long long sz = (long long)in_sizes[i];
        const float* p = (const float*)d_in[i];
        if (sz == (long long)B_ROWS * DIM && !x) x = p;
        else if (sz == (long long)DIM * TDICT) { if (!Wenc) Wenc = p; else Wdec = p; }
        else if (sz == TDICT) benc = p;
        else if (sz == DIM) bdec = p;
    }
    (void)out_size;

    static bool attr_set = false;
    if (!attr_set) {
        cudaFuncSetAttribute(gemm_hmma_kernel,
                             cudaFuncAttributeMaxDynamicSharedMemorySize, GEMM_SMEM);
        attr_set = true;
    }

    prep_x_kernel<<<B_ROWS, 256>>>(x, bdec);
    prep_w_kernel<<<dim3(TDICT / 32, DIM / 32), 256>>>(Wenc);
    gemm_hmma_kernel<<<dim3(B_ROWS / GBM, TDICT / GBN), 512, GEMM_SMEM>>>(benc);
    topk_rescue_kernel<<<B_ROWS, 256>>>(benc);
    decode_kernel<<<B_ROWS, 256>>>(Wdec, bdec, (float*)d_out);
}